// round 9
// baseline (speedup 1.0000x reference)
#include <cuda_runtime.h>
#include <cstdint>

#define Nn 100000
#define Ee 400000
#define Dd 300
#define Vv 3000
#define Gg 128
#define EPSv 1e-5f

// ---------------- scratch (device globals) ------------------------------------
__device__ __align__(16) float g_embA[(size_t)Vv * Dd];
__device__ __align__(16) float g_embB[(size_t)Vv * Dd];
__device__ __align__(16) float g_embC[(size_t)Vv * Dd];
__device__ __align__(16) float g_embD[(size_t)Vv * Dd];
__device__ __align__(16) float g_embF[(size_t)Vv * Dd];
__device__ __align__(16) float g_gsA [(size_t)Nn * Dd];
__device__ __align__(16) float g_gsB [(size_t)Nn * Dd];
__device__ __align__(16) float g_gsD [(size_t)Nn * Dd];
__device__ __align__(16) float g_gsF [(size_t)Nn * Dd];
__device__ __align__(16) float g_h   [(size_t)Ee * Dd];   // h1; later node2 hidden (first Nn rows)
__device__ __align__(16) float g_agg [(size_t)Nn * Dd];   // aggsum of h2
__device__ __align__(16) float g_xenc[(size_t)Nn * Dd];
__device__ __align__(16) float g_w2p [Dd * Dd];           // ew2 @ n1w1_hi
__device__ __align__(16) float g_w12 [Dd * Dd];           // n1w2 @ n2w1_hi
__device__ __align__(16) float g_wcat[Dd * 2 * Dd];       // [300][600] = [ew2 | w2p]
__device__ __align__(16) float g_bcat[2 * Dd];
__device__ __align__(16) float g_b2[Dd];
__device__ __align__(16) float g_bb[Dd];                  // n1b2 @ n2w1_hi
__device__ float g_cnt[Nn];
__device__ float g_sign[Ee];
__device__ float g_gsum[Gg], g_gsq[Gg], g_gcnt[Gg], g_gmean[Gg], g_grstd[Gg];

// ---------------- merged init ---------------------------------------------------
__global__ void k_init() {
    long long i = (long long)blockIdx.x * blockDim.x + threadIdx.x;
    long long stride = (long long)gridDim.x * blockDim.x;
    for (long long j = i; j < (long long)Nn * Dd; j += stride) g_agg[j] = 0.f;
    for (long long j = i; j < Nn; j += stride) g_cnt[j] = 0.f;
    for (long long j = i; j < Ee; j += stride) g_sign[j] = 1.f;
    if (i < Gg) { g_gsum[i] = 0.f; g_gsq[i] = 0.f; g_gcnt[i] = 0.f; }
}
__global__ void k_signset_cnt(const int* __restrict__ ase, const int* __restrict__ col) {
    int i = blockIdx.x * blockDim.x + threadIdx.x;
    if (i < Ee) atomicAdd(&g_cnt[col[i]], 1.f);
    if (i < Ee / 2) g_sign[ase[i]] = -1.f;
}

// ---------------- mma / cp.async / red helpers ---------------------------------
__device__ __forceinline__ void mma_tf32(float* c, unsigned a0, unsigned a1,
                                         unsigned a2, unsigned a3,
                                         unsigned b0, unsigned b1) {
    asm volatile(
        "mma.sync.aligned.m16n8k8.row.col.f32.tf32.tf32.f32 "
        "{%0,%1,%2,%3}, {%4,%5,%6,%7}, {%8,%9}, {%0,%1,%2,%3};"
        : "+f"(c[0]), "+f"(c[1]), "+f"(c[2]), "+f"(c[3])
        : "r"(a0), "r"(a1), "r"(a2), "r"(a3), "r"(b0), "r"(b1));
}
__device__ __forceinline__ void cpa16(unsigned int dst, const void* src, bool p) {
    int sz = p ? 16 : 0;
    asm volatile("cp.async.cg.shared.global [%0], [%1], 16, %2;"
                 :: "r"(dst), "l"(src), "r"(sz));
}
__device__ __forceinline__ void cpa_commit() {
    asm volatile("cp.async.commit_group;");
}
__device__ __forceinline__ void red_v2(float* p, float2 v) {
    asm volatile("red.global.add.v2.f32 [%0], {%1, %2};"
                 :: "l"(p), "f"(v.x), "f"(v.y) : "memory");
}

#define BMt 128
#define BNt 64
#define BKt 16
#define AS_STR 20
#define BS_STR 72
#define NCHUNK 19

// ---------------- old static-smem GEMM body (precompute only) -------------------
__device__ __forceinline__ void gemm_body0(
    int M, int Nout,
    const float* __restrict__ A, const float* __restrict__ W, int ldw,
    float* __restrict__ out0)
{
    __shared__ float As[2][BMt * AS_STR];
    __shared__ float Bs[2][BKt * BS_STR];

    const int tid = threadIdx.x;
    const int lane = tid & 31, grp = lane >> 2, tig = lane & 3;
    const int w = tid >> 5;
    const int wm = (w & 3) * 32, wn = (w >> 2) * 32;
    const int tile_n = blockIdx.x * BNt;
    const int tile_m = blockIdx.y * BMt;

    const float* rp[2];
#pragma unroll
    for (int it = 0; it < 2; ++it) {
        int m = (tid >> 2) + it * 64;
        int gm = tile_m + m; if (gm >= M) gm = M - 1;
        rp[it] = A + (size_t)gm * Dd;
    }
    const int ag  = (tid & 3) * 4;
    const int bk  = tid >> 4;
    const int bn4 = (tid & 15) * 4;

    unsigned int sA[2][2], sB[2];
#pragma unroll
    for (int b = 0; b < 2; ++b) {
#pragma unroll
        for (int it = 0; it < 2; ++it) {
            int m = (tid >> 2) + it * 64;
            sA[b][it] = (unsigned int)__cvta_generic_to_shared(&As[b][m * AS_STR + ag]);
        }
        sB[b] = (unsigned int)__cvta_generic_to_shared(&Bs[b][bk * BS_STR + bn4]);
    }

    float acc[2][4][4];
#pragma unroll
    for (int mt = 0; mt < 2; mt++)
#pragma unroll
        for (int nt = 0; nt < 4; nt++)
#pragma unroll
            for (int q = 0; q < 4; q++) acc[mt][nt][q] = 0.f;

    auto load_chunk = [&](int c, int b) {
        int koff = c * BKt;
        int width = 300 - koff; if (width > BKt) width = BKt;
        cpa16(sA[b][0], rp[0] + koff + ag, ag < width);
        cpa16(sA[b][1], rp[1] + koff + ag, ag < width);
        bool pb = (bk < width) && (tile_n + bn4 < Nout);
        cpa16(sB[b], W + (size_t)(koff + bk) * ldw + tile_n + bn4, pb);
    };

    load_chunk(0, 0);
    cpa_commit();

    for (int c = 0; c < NCHUNK; ++c) {
        if (c + 1 < NCHUNK) { load_chunk(c + 1, (c + 1) & 1); cpa_commit(); }
        if (c + 1 < NCHUNK) asm volatile("cp.async.wait_group 1;");
        else                asm volatile("cp.async.wait_group 0;");
        __syncthreads();

        const float* as = As[c & 1];
        const float* bs = Bs[c & 1];
#pragma unroll
        for (int ks = 0; ks < 2; ++ks) {
            const int k0 = ks * 8;
            unsigned af[2][4], bf[4][2];
#pragma unroll
            for (int mt = 0; mt < 2; ++mt) {
                int r0 = (wm + mt * 16 + grp) * AS_STR;
                af[mt][0] = __float_as_uint(as[r0 + k0 + tig]);
                af[mt][1] = __float_as_uint(as[r0 + 8 * AS_STR + k0 + tig]);
                af[mt][2] = __float_as_uint(as[r0 + k0 + tig + 4]);
                af[mt][3] = __float_as_uint(as[r0 + 8 * AS_STR + k0 + tig + 4]);
            }
#pragma unroll
            for (int nt = 0; nt < 4; ++nt) {
                bf[nt][0] = __float_as_uint(bs[(k0 + tig) * BS_STR + wn + nt * 8 + grp]);
                bf[nt][1] = __float_as_uint(bs[(k0 + tig + 4) * BS_STR + wn + nt * 8 + grp]);
            }
#pragma unroll
            for (int mt = 0; mt < 2; ++mt)
#pragma unroll
                for (int nt = 0; nt < 4; ++nt)
                    mma_tf32(acc[mt][nt], af[mt][0], af[mt][1], af[mt][2], af[mt][3],
                             bf[nt][0], bf[nt][1]);
        }
        __syncthreads();
    }

#pragma unroll
    for (int mt = 0; mt < 2; ++mt) {
#pragma unroll
        for (int half = 0; half < 2; ++half) {
            int gm = tile_m + wm + mt * 16 + grp + half * 8;
            if (gm >= M) continue;
#pragma unroll
            for (int nt = 0; nt < 4; ++nt) {
                int gn = tile_n + wn + nt * 8 + tig * 2;
                if (gn >= Nout) continue;
                float2 v = make_float2(acc[mt][nt][half * 2], acc[mt][nt][half * 2 + 1]);
                *(float2*)&out0[(size_t)gm * Dd + gn] = v;
            }
        }
    }
}

struct Bat5 { const float* A[5]; const float* W[5]; float* O[5]; };

__global__ __launch_bounds__(256) void k_gemm_bat(int M, int Nout, Bat5 bat, int ldw) {
    int z = blockIdx.z;
    gemm_body0(M, Nout, bat.A[z], bat.W[z], ldw, bat.O[z]);
}

// ---------------- persistent-A GEMM: A resident, loop over all N-tiles ----------
// smem: A [128][308] (conflict-free: 308%32=20, r*20 mod 32 distinct over 8 rows)
//       B ring of 3 stages [16][72]; prefetch distance 2 -> ONE barrier per chunk.
// MODE 0: out0 = v + bias
// MODE 3: dual Nout=600: gn<300 -> out0 = v+bias; gn>=300 ->
//         t = relu(v+bias+add_src[add_idx[m]*300+gn-300]); red.v2(out1[scat[m]*300+gn-300], t)
// MODE 5: c=cnt[m]; out0 = relu(v/max(c,1) + bias + add_src[m*300+gn] + (c>0?bias2:0))
#define PA_STR 308
#define PSMEM ((BMt * PA_STR + 3 * BKt * BS_STR) * 4)

template <int MODE>
__global__ __launch_bounds__(256) void k_gemm_pers(
    int M, int Nout,
    const float* __restrict__ A,
    const float* __restrict__ W, int ldw,
    const float* __restrict__ bias, const float* __restrict__ bias2,
    float* __restrict__ out0, float* __restrict__ out1,
    const float* __restrict__ add_src, const int* __restrict__ add_idx,
    const int* __restrict__ scat_idx, const float* __restrict__ cntv)
{
    extern __shared__ float sm[];
    float* As = sm;                           // [128][PA_STR]
    float* Bs = sm + BMt * PA_STR;            // 3 x [BKt][BS_STR]

    const int tid = threadIdx.x;
    const int lane = tid & 31, grp = lane >> 2, tig = lane & 3;
    const int w = tid >> 5;
    const int wm = (w & 3) * 32, wn = (w >> 2) * 32;
    const int tile_m = blockIdx.x * BMt;

    // A loader: 2 rows/thread, 16B piece at ag within each 16-wide chunk
    const float* rp[2];
    unsigned aDst[2];
#pragma unroll
    for (int it = 0; it < 2; ++it) {
        int m = (tid >> 2) + it * 64;
        int gm = tile_m + m; if (gm >= M) gm = M - 1;
        rp[it] = A + (size_t)gm * Dd;
        aDst[it] = (unsigned)__cvta_generic_to_shared(&As[m * PA_STR]);
    }
    const int ag  = (tid & 3) * 4;
    const int bk  = tid >> 4;
    const int bn4 = (tid & 15) * 4;
    unsigned bDst[3];
#pragma unroll
    for (int s = 0; s < 3; ++s)
        bDst[s] = (unsigned)__cvta_generic_to_shared(&Bs[s * BKt * BS_STR + bk * BS_STR + bn4]);

    const int nT = (Nout + BNt - 1) / BNt;
    const int T = nT * NCHUNK;

    // ---- load ALL of A (19 chunks) ----
#pragma unroll
    for (int c = 0; c < NCHUNK; ++c) {
        int koff = c * BKt;
        int width = 300 - koff; if (width > BKt) width = BKt;
        cpa16(aDst[0] + (koff + ag) * 4, rp[0] + koff + ag, ag < width);
        cpa16(aDst[1] + (koff + ag) * 4, rp[1] + koff + ag, ag < width);
    }
    auto loadB = [&](int t) {
        int n = t / NCHUNK, c = t - n * NCHUNK;
        int koff = c * BKt;
        int width = 300 - koff; if (width > BKt) width = BKt;
        int tn = n * BNt;
        cpa16(bDst[t % 3], W + (size_t)(koff + bk) * ldw + tn + bn4,
              (bk < width) && (tn + bn4) < Nout);
    };
    loadB(0); cpa_commit();          // group 0 = A + B(0)
    if (T > 1) { loadB(1); cpa_commit(); }

    float acc[2][4][4];
#pragma unroll
    for (int mt = 0; mt < 2; mt++)
#pragma unroll
        for (int nt = 0; nt < 4; nt++)
#pragma unroll
            for (int q = 0; q < 4; q++) acc[mt][nt][q] = 0.f;

    for (int t = 0; t < T; ++t) {
        if (t + 1 < T) asm volatile("cp.async.wait_group 1;");
        else           asm volatile("cp.async.wait_group 0;");
        __syncthreads();                           // all warps done with chunk t-1
        if (t + 2 < T) { loadB(t + 2); cpa_commit(); }  // targets buf read at t-1: safe

        const int n = t / NCHUNK, c = t - n * NCHUNK;
        const int koff = c * BKt;
        const int width = (300 - koff) < BKt ? (300 - koff) : BKt;
        const float* bs = Bs + (t % 3) * BKt * BS_STR;
#pragma unroll
        for (int ks = 0; ks < 2; ++ks) {
            if (ks * 8 >= width) break;
            const int k0 = koff + ks * 8;
            unsigned af[2][4], bf[4][2];
#pragma unroll
            for (int mt = 0; mt < 2; ++mt) {
                int r0 = (wm + mt * 16 + grp) * PA_STR;
                af[mt][0] = __float_as_uint(As[r0 + k0 + tig]);
                af[mt][1] = __float_as_uint(As[r0 + 8 * PA_STR + k0 + tig]);
                af[mt][2] = __float_as_uint(As[r0 + k0 + tig + 4]);
                af[mt][3] = __float_as_uint(As[r0 + 8 * PA_STR + k0 + tig + 4]);
            }
            const int kb = ks * 8;
#pragma unroll
            for (int nt = 0; nt < 4; ++nt) {
                bf[nt][0] = __float_as_uint(bs[(kb + tig) * BS_STR + wn + nt * 8 + grp]);
                bf[nt][1] = __float_as_uint(bs[(kb + tig + 4) * BS_STR + wn + nt * 8 + grp]);
            }
#pragma unroll
            for (int mt = 0; mt < 2; ++mt)
#pragma unroll
                for (int nt = 0; nt < 4; ++nt)
                    mma_tf32(acc[mt][nt], af[mt][0], af[mt][1], af[mt][2], af[mt][3],
                             bf[nt][0], bf[nt][1]);
        }

        if (c == NCHUNK - 1) {
            // ---- epilogue for n-tile ----
            const int tile_n = n * BNt;
            const bool hi_half = (tile_n + wn + 31) >= Dd;
#pragma unroll
            for (int mt = 0; mt < 2; ++mt) {
#pragma unroll
                for (int half = 0; half < 2; ++half) {
                    int gm = tile_m + wm + mt * 16 + grp + half * 8;
                    if (gm >= M) continue;
                    int ai = 0, si = 0;
                    float ct = 0.f, inv = 0.f;
                    if (MODE == 3) {
                        if (hi_half) { ai = __ldg(&add_idx[gm]); si = __ldg(&scat_idx[gm]); }
                    }
                    if (MODE == 5) { ct = __ldg(&cntv[gm]); inv = 1.f / fmaxf(ct, 1.f); }
#pragma unroll
                    for (int nt = 0; nt < 4; ++nt) {
                        int gn = tile_n + wn + nt * 8 + tig * 2;
                        if (gn >= Nout) continue;
                        float2 v = make_float2(acc[mt][nt][half * 2], acc[mt][nt][half * 2 + 1]);
                        if (MODE == 0) {
                            float2 b = __ldg((const float2*)&bias[gn]);
                            v.x += b.x; v.y += b.y;
                            *(float2*)&out0[(size_t)gm * Dd + gn] = v;
                        } else if (MODE == 3) {
                            float2 b = __ldg((const float2*)&bias[gn]);
                            v.x += b.x; v.y += b.y;
                            if (gn < Dd) {
                                *(float2*)&out0[(size_t)gm * Dd + gn] = v;
                            } else {
                                int gn2 = gn - Dd;
                                float2 a = *(const float2*)&add_src[(size_t)ai * Dd + gn2];
                                v.x = fmaxf(v.x + a.x, 0.f);
                                v.y = fmaxf(v.y + a.y, 0.f);
                                red_v2(&out1[(size_t)si * Dd + gn2], v);
                            }
                        } else {  // MODE 5
                            float2 b = __ldg((const float2*)&bias[gn]);
                            float2 a = *(const float2*)&add_src[(size_t)gm * Dd + gn];
                            float2 b2 = make_float2(0.f, 0.f);
                            if (ct > 0.f) b2 = __ldg((const float2*)&bias2[gn]);
                            v.x = fmaxf(v.x * inv + b.x + b2.x + a.x, 0.f);
                            v.y = fmaxf(v.y * inv + b.y + b2.y + a.y, 0.f);
                            *(float2*)&out0[(size_t)gm * Dd + gn] = v;
                        }
                    }
                }
            }
            // reset accumulators for next n-tile
#pragma unroll
            for (int mt = 0; mt < 2; mt++)
#pragma unroll
                for (int nt = 0; nt < 4; nt++)
#pragma unroll
                    for (int q = 0; q < 4; q++) acc[mt][nt][q] = 0.f;
        }
    }
}

// ---------------- gather-sum of 4 pre-transformed tables (float4/thread) -------
__global__ void k_gsum4(const int* __restrict__ tok) {
    int i = blockIdx.x * blockDim.x + threadIdx.x;
    if (i >= Nn * 75) return;
    int n = i / 75, d0 = (i - n * 75) * 4;
    int4 t = ((const int4*)tok)[n];
    size_t o0 = (size_t)t.x * Dd + d0, o1 = (size_t)t.y * Dd + d0;
    size_t o2 = (size_t)t.z * Dd + d0, o3 = (size_t)t.w * Dd + d0;
    size_t di = (size_t)n * Dd + d0;
    float4 r, a0, a1, a2, a3;
    a0 = *(const float4*)&g_embA[o0]; a1 = *(const float4*)&g_embA[o1];
    a2 = *(const float4*)&g_embA[o2]; a3 = *(const float4*)&g_embA[o3];
    r.x = a0.x + a1.x + a2.x + a3.x; r.y = a0.y + a1.y + a2.y + a3.y;
    r.z = a0.z + a1.z + a2.z + a3.z; r.w = a0.w + a1.w + a2.w + a3.w;
    *(float4*)&g_gsA[di] = r;
    a0 = *(const float4*)&g_embB[o0]; a1 = *(const float4*)&g_embB[o1];
    a2 = *(const float4*)&g_embB[o2]; a3 = *(const float4*)&g_embB[o3];
    r.x = a0.x + a1.x + a2.x + a3.x; r.y = a0.y + a1.y + a2.y + a3.y;
    r.z = a0.z + a1.z + a2.z + a3.z; r.w = a0.w + a1.w + a2.w + a3.w;
    *(float4*)&g_gsB[di] = r;
    a0 = *(const float4*)&g_embD[o0]; a1 = *(const float4*)&g_embD[o1];
    a2 = *(const float4*)&g_embD[o2]; a3 = *(const float4*)&g_embD[o3];
    r.x = a0.x + a1.x + a2.x + a3.x; r.y = a0.y + a1.y + a2.y + a3.y;
    r.z = a0.z + a1.z + a2.z + a3.z; r.w = a0.w + a1.w + a2.w + a3.w;
    *(float4*)&g_gsD[di] = r;
    a0 = *(const float4*)&g_embF[o0]; a1 = *(const float4*)&g_embF[o1];
    a2 = *(const float4*)&g_embF[o2]; a3 = *(const float4*)&g_embF[o3];
    r.x = a0.x + a1.x + a2.x + a3.x; r.y = a0.y + a1.y + a2.y + a3.y;
    r.z = a0.z + a1.z + a2.z + a3.z; r.w = a0.w + a1.w + a2.w + a3.w;
    *(float4*)&g_gsF[di] = r;
}

// ---------------- edge layer-1 elementwise (float4/thread) ----------------------
__global__ void k_edge_l1(const int* __restrict__ ea_tok,
                          const int* __restrict__ row, const int* __restrict__ col,
                          const float* __restrict__ eb1) {
    int i = blockIdx.x * blockDim.x + threadIdx.x;
    if (i >= Ee * 75) return;
    int e = i / 75, d0 = (i - e * 75) * 4;
    int4 t = ((const int4*)ea_tok)[e];
    float4 c0 = *(const float4*)&g_embC[(size_t)t.x * Dd + d0];
    float4 c1 = *(const float4*)&g_embC[(size_t)t.y * Dd + d0];
    float4 c2 = *(const float4*)&g_embC[(size_t)t.z * Dd + d0];
    float4 c3 = *(const float4*)&g_embC[(size_t)t.w * Dd + d0];
    int r = __ldg(&row[e]), q = __ldg(&col[e]);
    float sg = g_sign[e];
    float4 ga = *(const float4*)&g_gsA[(size_t)r * Dd + d0];
    float4 gb = *(const float4*)&g_gsB[(size_t)q * Dd + d0];
    float4 bb = __ldg((const float4*)&eb1[d0]);
    float4 o;
    o.x = fmaxf(ga.x + gb.x + (c0.x + c1.x + c2.x + c3.x) * sg + bb.x, 0.f);
    o.y = fmaxf(ga.y + gb.y + (c0.y + c1.y + c2.y + c3.y) * sg + bb.y, 0.f);
    o.z = fmaxf(ga.z + gb.z + (c0.z + c1.z + c2.z + c3.z) * sg + bb.z, 0.f);
    o.w = fmaxf(ga.w + gb.w + (c0.w + c1.w + c2.w + c3.w) * sg + bb.w, 0.f);
    *(float4*)&g_h[(size_t)e * Dd + d0] = o;
}

// ---------------- tiny precompute helpers ---------------------------------------
__global__ void k_vecmat2(const float* __restrict__ eb2, const float* __restrict__ n1w1,
                          const float* __restrict__ n1b1, const float* __restrict__ n1b2,
                          const float* __restrict__ n2w1) {
    int n = blockIdx.x * blockDim.x + threadIdx.x;
    if (n < Dd) {
        float s = n1b1[n];
        for (int k = 0; k < Dd; k++) s += eb2[k] * n1w1[(size_t)(Dd + k) * Dd + n];
        g_b2[n] = s;
    } else if (n < 2 * Dd) {
        int m = n - Dd;
        float s = 0.f;
        for (int k = 0; k < Dd; k++) s += n1b2[k] * n2w1[(size_t)(Dd + k) * Dd + m];
        g_bb[m] = s;
    }
}
__global__ void k_build_wcat(const float* __restrict__ ew2, const float* __restrict__ eb2) {
    int i = blockIdx.x * blockDim.x + threadIdx.x;
    if (i < Dd * 2 * Dd) {
        int k = i / (2 * Dd), n = i - k * 2 * Dd;
        g_wcat[i] = (n < Dd) ? ew2[(size_t)k * Dd + n] : g_w2p[(size_t)k * Dd + (n - Dd)];
    }
    if (i < 2 * Dd) g_bcat[i] = (i < Dd) ? eb2[i] : g_b2[i - Dd];
}

// ---------------- graph layer norm ----------------------------------------------
__global__ void k_stats(const int* __restrict__ batch) {
    int n = blockIdx.x;
    float s = 0.f, q = 0.f;
    for (int d = threadIdx.x; d < Dd; d += 128) {
        float v = g_xenc[(size_t)n * Dd + d];
        s += v; q += v * v;
    }
#pragma unroll
    for (int o = 16; o; o >>= 1) {
        s += __shfl_down_sync(0xFFFFFFFFu, s, o);
        q += __shfl_down_sync(0xFFFFFFFFu, q, o);
    }
    __shared__ float ss[4], qq[4];
    int w = threadIdx.x >> 5, l = threadIdx.x & 31;
    if (l == 0) { ss[w] = s; qq[w] = q; }
    __syncthreads();
    if (threadIdx.x == 0) {
        s = ss[0] + ss[1] + ss[2] + ss[3];
        q = qq[0] + qq[1] + qq[2] + qq[3];
        int g = batch[n];
        atomicAdd(&g_gsum[g], s);
        atomicAdd(&g_gsq[g], q);
        atomicAdd(&g_gcnt[g], 1.f);
    }
}
__global__ void k_finalize() {
    int g = threadIdx.x;
    if (g < Gg) {
        float denom = fmaxf(g_gcnt[g] * (float)Dd, 1.f);
        float mean = g_gsum[g] / denom;
        float var = g_gsq[g] / denom - mean * mean;
        g_gmean[g] = mean;
        g_grstd[g] = rsqrtf(var + EPSv);
    }
}
__global__ void k_apply(const int* __restrict__ batch,
                        const float* __restrict__ lnw, const float* __restrict__ lnb,
                        float* __restrict__ out) {
    int i = blockIdx.x * blockDim.x + threadIdx.x;
    if (i >= Nn * 75) return;
    int n = i / 75, d0 = (i - n * 75) * 4;
    int g = __ldg(&batch[n]);
    float mean = g_gmean[g], rstd = g_grstd[g];
    float4 x = *(const float4*)&g_xenc[(size_t)n * Dd + d0];
    float4 wv = __ldg((const float4*)&lnw[d0]);
    float4 bv = __ldg((const float4*)&lnb[d0]);
    float4 o;
    o.x = (x.x - mean) * rstd * wv.x + bv.x;
    o.y = (x.y - mean) * rstd * wv.y + bv.y;
    o.z = (x.z - mean) * rstd * wv.z + bv.z;
    o.w = (x.w - mean) * rstd * wv.w + bv.w;
    *(float4*)&out[(size_t)n * Dd + d0] = o;
}

// ---------------- launch ---------------------------------------------------------
static float* symf(const void* s) {
    void* p = nullptr;
    cudaGetSymbolAddress(&p, s);
    return (float*)p;
}

extern "C" void kernel_launch(void* const* d_in, const int* in_sizes, int n_in,
                              void* d_out, int out_size) {
    const int*   x_tok  = (const int*)d_in[0];
    const int*   ea_tok = (const int*)d_in[1];
    const int*   eidx   = (const int*)d_in[2];
    const int*   ase    = (const int*)d_in[3];
    const int*   batch  = (const int*)d_in[4];
    const float* emb    = (const float*)d_in[5];
    const float* ew1  = (const float*)d_in[6];
    const float* eb1  = (const float*)d_in[7];
    const float* ew2  = (const float*)d_in[8];
    const float* eb2  = (const float*)d_in[9];
    const float* n1w1 = (const float*)d_in[10];
    const float* n1b1 = (const float*)d_in[11];
    const float* n1w2 = (const float*)d_in[12];
    const float* n1b2 = (const float*)d_in[13];
    const float* n2w1 = (const float*)d_in[14];
    const float* n2b1 = (const float*)d_in[15];
    const float* n2w2 = (const float*)d_in[16];
    const float* n2b2 = (const float*)d_in[17];
    const float* lnw  = (const float*)d_in[18];
    const float* lnb  = (const float*)d_in[19];

    const int* row = eidx;
    const int* col = eidx + Ee;

    float* out = (float*)d_out;
    float* edge_out = out + (size_t)Nn * Dd;

    float* pembA = symf(g_embA); float* pembB = symf(g_embB);
    float* pembC = symf(g_embC); float* pembD = symf(g_embD);
    float* pembF = symf(g_embF);
    float* pgsD  = symf(g_gsD);  float* pgsF  = symf(g_gsF);
    float* ph    = symf(g_h);
    float* pagg  = symf(g_agg);  float* pxenc = symf(g_xenc);
    float* pw2p  = symf(g_w2p);  float* pw12  = symf(g_w12);
    float* pwcat = symf(g_wcat); float* pbcat = symf(g_bcat);
    float* pcnt  = symf(g_cnt);

    cudaFuncSetAttribute(k_gemm_pers<0>, cudaFuncAttributeMaxDynamicSharedMemorySize, PSMEM);
    cudaFuncSetAttribute(k_gemm_pers<3>, cudaFuncAttributeMaxDynamicSharedMemorySize, PSMEM);
    cudaFuncSetAttribute(k_gemm_pers<5>, cudaFuncAttributeMaxDynamicSharedMemorySize, PSMEM);

    const int T256 = 256;

    // init + sign/cnt
    k_init<<<2048, T256>>>();
    k_signset_cnt<<<(Ee + T256 - 1) / T256, T256>>>(ase, col);

    // batched emb precompute: emb @ {Wa, Wb, Wc, Wd, Wf}
    {
        Bat5 b;
        b.A[0] = emb; b.A[1] = emb; b.A[2] = emb; b.A[3] = emb; b.A[4] = emb;
        b.W[0] = ew1; b.W[1] = ew1 + 300*300; b.W[2] = ew1 + 600*300;
        b.W[3] = n1w1; b.W[4] = n2w1;
        b.O[0] = pembA; b.O[1] = pembB; b.O[2] = pembC; b.O[3] = pembD; b.O[4] = pembF;
        k_gemm_bat<<<dim3(5, (Vv + BMt - 1) / BMt, 5), T256>>>(Vv, Dd, b, Dd);
    }
    // batched small GEMMs: w2p = ew2 @ n1w1_hi ; w12 = n1w2 @ n2w1_hi
    {
        Bat5 b;
        b.A[0] = ew2;  b.A[1] = n1w2; b.A[2] = ew2; b.A[3] = ew2; b.A[4] = ew2;
        b.W[0] = n1w1 + 300*300; b.W[1] = n2w1 + 300*300;
        b.W[2] = b.W[0]; b.W[3] = b.W[0]; b.W[4] = b.W[0];
        b.O[0] = pw2p; b.O[1] = pw12; b.O[2] = pw2p; b.O[3] = pw2p; b.O[4] = pw2p;
        k_gemm_bat<<<dim3(5, (Dd + BMt - 1) / BMt, 2), T256>>>(Dd, Dd, b, Dd);
    }
    // b2 + bb ; wcat assembly
    k_vecmat2<<<3, T256>>>(eb2, n1w1, n1b1, n1b2, n2w1);
    k_build_wcat<<<(Dd * 2 * Dd + T256 - 1) / T256, T256>>>(ew2, eb2);

    // gather-sums + edge layer-1
    k_gsum4<<<(Nn * 75 + T256 - 1) / T256, T256>>>(x_tok);
    k_edge_l1<<<(Ee * 75 + T256 - 1) / T256, T256>>>(ea_tok, row, col, eb1);

    // dual GEMM (persistent-A): edge_enc + h2 scattered into aggsum
    k_gemm_pers<3><<<Ee / BMt, T256, PSMEM>>>(Ee, 2 * Dd, ph, pwcat, 2 * Dd,
                                              pbcat, nullptr, edge_out, pagg,
                                              pgsD, row, col, nullptr);
    // node2 layer-1 (persistent-A)
    int gridN = (Nn + BMt - 1) / BMt;
    k_gemm_pers<5><<<gridN, T256, PSMEM>>>(Nn, Dd, pagg, pw12, Dd, n2b1, symf(g_bb),
                                           ph, nullptr, pgsF, nullptr, nullptr, pcnt);
    // node2 layer-2 (persistent-A)
    k_gemm_pers<0><<<gridN, T256, PSMEM>>>(Nn, Dd, ph, n2w2, Dd, n2b2, nullptr,
                                           pxenc, nullptr, nullptr, nullptr, nullptr, nullptr);

    // graph layer norm
    k_stats<<<Nn, 128>>>(batch);
    k_finalize<<<1, 128>>>();
    k_apply<<<(Nn * 75 + T256 - 1) / T256, T256>>>(batch, lnw, lnb, out);
}

// round 10
// speedup vs baseline: 1.8018x; 1.8018x over previous
#include <cuda_runtime.h>
#include <cstdint>

#define Nn 100000
#define Ee 400000
#define Dd 300
#define Vv 3000
#define Gg 128
#define EPSv 1e-5f

// ---------------- scratch (device globals) ------------------------------------
__device__ __align__(16) float g_embA[(size_t)Vv * Dd];
__device__ __align__(16) float g_embB[(size_t)Vv * Dd];
__device__ __align__(16) float g_embC[(size_t)Vv * Dd];
__device__ __align__(16) float g_embD[(size_t)Vv * Dd];
__device__ __align__(16) float g_embF[(size_t)Vv * Dd];
__device__ __align__(16) float g_gsA [(size_t)Nn * Dd];
__device__ __align__(16) float g_gsB [(size_t)Nn * Dd];
__device__ __align__(16) float g_gsD [(size_t)Nn * Dd];
__device__ __align__(16) float g_gsF [(size_t)Nn * Dd];
__device__ __align__(16) float g_h   [(size_t)Ee * Dd];   // h1; later node2 hidden (first Nn rows)
__device__ __align__(16) float g_agg [(size_t)Nn * Dd];   // aggsum of h2
__device__ __align__(16) float g_xenc[(size_t)Nn * Dd];
__device__ __align__(16) float g_w2p [Dd * Dd];           // ew2 @ n1w1_hi
__device__ __align__(16) float g_w12 [Dd * Dd];           // n1w2 @ n2w1_hi
__device__ __align__(16) float g_wcat[Dd * 2 * Dd];       // [300][600] = [ew2 | w2p]
__device__ __align__(16) float g_bcat[2 * Dd];
__device__ __align__(16) float g_bb[Dd];                  // n1b2 @ n2w1_hi
__device__ float g_cnt[Nn];
__device__ float g_sign[Ee];
__device__ float g_gsum[Gg], g_gsq[Gg], g_gcnt[Gg], g_gmean[Gg], g_grstd[Gg];

// ---------------- merged init (float4 stores) -----------------------------------
__global__ void k_init() {
    long long i = (long long)blockIdx.x * blockDim.x + threadIdx.x;
    long long stride = (long long)gridDim.x * blockDim.x;
    float4 z = make_float4(0.f, 0.f, 0.f, 0.f);
    for (long long j = i; j < (long long)Nn * Dd / 4; j += stride)
        ((float4*)g_agg)[j] = z;
    for (long long j = i; j < Nn / 4; j += stride)
        ((float4*)g_cnt)[j] = z;
    for (long long j = i; j < Ee / 4; j += stride)
        ((float4*)g_sign)[j] = make_float4(1.f, 1.f, 1.f, 1.f);
    if (i < Gg) { g_gsum[i] = 0.f; g_gsq[i] = 0.f; g_gcnt[i] = 0.f; }
}
__global__ void k_signset_cnt(const int* __restrict__ ase, const int* __restrict__ col) {
    int i = blockIdx.x * blockDim.x + threadIdx.x;
    if (i < Ee) atomicAdd(&g_cnt[col[i]], 1.f);
    if (i < Ee / 2) g_sign[ase[i]] = -1.f;
}

// ---------------- mma / cp.async / red helpers ---------------------------------
__device__ __forceinline__ void mma_tf32(float* c, unsigned a0, unsigned a1,
                                         unsigned a2, unsigned a3,
                                         unsigned b0, unsigned b1) {
    asm volatile(
        "mma.sync.aligned.m16n8k8.row.col.f32.tf32.tf32.f32 "
        "{%0,%1,%2,%3}, {%4,%5,%6,%7}, {%8,%9}, {%0,%1,%2,%3};"
        : "+f"(c[0]), "+f"(c[1]), "+f"(c[2]), "+f"(c[3])
        : "r"(a0), "r"(a1), "r"(a2), "r"(a3), "r"(b0), "r"(b1));
}
__device__ __forceinline__ void cpa16(unsigned int dst, const void* src, bool p) {
    int sz = p ? 16 : 0;
    asm volatile("cp.async.cg.shared.global [%0], [%1], 16, %2;"
                 :: "r"(dst), "l"(src), "r"(sz));
}
__device__ __forceinline__ void cpa_commit() {
    asm volatile("cp.async.commit_group;");
}
__device__ __forceinline__ void red_v2(float* p, float2 v) {
    asm volatile("red.global.add.v2.f32 [%0], {%1, %2};"
                 :: "l"(p), "f"(v.x), "f"(v.y) : "memory");
}

// ---------------- tensor-core GEMM body, K fixed = 300 (r8 proven config) -------
// BM=128, BN=64, BK=16, static smem double buffer, warp tile 32x32.
// MODE 0: out0 = v (+bias)
// MODE 3: dual Nout=600 (M%128==0): gn<300 -> out0 = v+bias; gn>=300 ->
//         t = relu(v+bias+add_src[add_idx[m]*300+gn-300]); red.v2(out1[scat[m]*300+gn-300], t)
// MODE 5: c=cnt[m]; out0 = relu(v/max(c,1) + bias + add_src[m*300+gn] + (c>0?bias2:0))
#define BMt 128
#define BNt 64
#define BKt 16
#define AS_STR 20
#define BS_STR 72
#define NCHUNK 19

template <int MODE>
__device__ __forceinline__ void gemm_body(
    int M, int Nout,
    const float* __restrict__ A, const int* __restrict__ aidx,
    const float* __restrict__ W, int ldw,
    const float* __restrict__ bias, const float* __restrict__ bias2,
    float* __restrict__ out0, float* __restrict__ out1,
    const float* __restrict__ add_src, const int* __restrict__ add_idx,
    const int* __restrict__ scat_idx, const float* __restrict__ cntv)
{
    __shared__ float As[2][BMt * AS_STR];
    __shared__ float Bs[2][BKt * BS_STR];

    const int tid = threadIdx.x;
    const int lane = tid & 31, grp = lane >> 2, tig = lane & 3;
    const int w = tid >> 5;
    const int wm = (w & 3) * 32, wn = (w >> 2) * 32;
    const int tile_n = blockIdx.x * BNt;
    const int tile_m = blockIdx.y * BMt;

    const float* rp[2];
#pragma unroll
    for (int it = 0; it < 2; ++it) {
        int m = (tid >> 2) + it * 64;
        int gm = tile_m + m; if (gm >= M) gm = M - 1;
        int r = aidx ? __ldg(&aidx[gm]) : gm;
        rp[it] = A + (size_t)r * Dd;
    }
    const int ag  = (tid & 3) * 4;
    const int bk  = tid >> 4;
    const int bn4 = (tid & 15) * 4;

    unsigned int sA[2][2], sB[2];
#pragma unroll
    for (int b = 0; b < 2; ++b) {
#pragma unroll
        for (int it = 0; it < 2; ++it) {
            int m = (tid >> 2) + it * 64;
            sA[b][it] = (unsigned int)__cvta_generic_to_shared(&As[b][m * AS_STR + ag]);
        }
        sB[b] = (unsigned int)__cvta_generic_to_shared(&Bs[b][bk * BS_STR + bn4]);
    }

    float acc[2][4][4];
#pragma unroll
    for (int mt = 0; mt < 2; mt++)
#pragma unroll
        for (int nt = 0; nt < 4; nt++)
#pragma unroll
            for (int q = 0; q < 4; q++) acc[mt][nt][q] = 0.f;

    auto load_chunk = [&](int c, int b) {
        int koff = c * BKt;
        int width = 300 - koff; if (width > BKt) width = BKt;
        cpa16(sA[b][0], rp[0] + koff + ag, ag < width);
        cpa16(sA[b][1], rp[1] + koff + ag, ag < width);
        bool pb = (bk < width) && (tile_n + bn4 < Nout);
        cpa16(sB[b], W + (size_t)(koff + bk) * ldw + tile_n + bn4, pb);
    };

    load_chunk(0, 0);
    cpa_commit();

    for (int c = 0; c < NCHUNK; ++c) {
        if (c + 1 < NCHUNK) { load_chunk(c + 1, (c + 1) & 1); cpa_commit(); }
        if (c + 1 < NCHUNK) asm volatile("cp.async.wait_group 1;");
        else                asm volatile("cp.async.wait_group 0;");
        __syncthreads();

        const float* as = As[c & 1];
        const float* bs = Bs[c & 1];
#pragma unroll
        for (int ks = 0; ks < 2; ++ks) {
            const int k0 = ks * 8;
            unsigned af[2][4], bf[4][2];
#pragma unroll
            for (int mt = 0; mt < 2; ++mt) {
                int r0 = (wm + mt * 16 + grp) * AS_STR;
                af[mt][0] = __float_as_uint(as[r0 + k0 + tig]);
                af[mt][1] = __float_as_uint(as[r0 + 8 * AS_STR + k0 + tig]);
                af[mt][2] = __float_as_uint(as[r0 + k0 + tig + 4]);
                af[mt][3] = __float_as_uint(as[r0 + 8 * AS_STR + k0 + tig + 4]);
            }
#pragma unroll
            for (int nt = 0; nt < 4; ++nt) {
                bf[nt][0] = __float_as_uint(bs[(k0 + tig) * BS_STR + wn + nt * 8 + grp]);
                bf[nt][1] = __float_as_uint(bs[(k0 + tig + 4) * BS_STR + wn + nt * 8 + grp]);
            }
#pragma unroll
            for (int mt = 0; mt < 2; ++mt)
#pragma unroll
                for (int nt = 0; nt < 4; ++nt)
                    mma_tf32(acc[mt][nt], af[mt][0], af[mt][1], af[mt][2], af[mt][3],
                             bf[nt][0], bf[nt][1]);
        }
        __syncthreads();
    }

    // ---- epilogue (pairs: gn even, never straddles 300) ----
    const bool hi_half = (tile_n + wn + 31) >= Dd;
#pragma unroll
    for (int mt = 0; mt < 2; ++mt) {
#pragma unroll
        for (int half = 0; half < 2; ++half) {
            int gm = tile_m + wm + mt * 16 + grp + half * 8;
            if (gm >= M) continue;
            int ai = 0, si = 0;
            float ct = 0.f, inv = 0.f;
            if (MODE == 3) {
                if (hi_half) { ai = __ldg(&add_idx[gm]); si = __ldg(&scat_idx[gm]); }
            }
            if (MODE == 5) { ct = __ldg(&cntv[gm]); inv = 1.f / fmaxf(ct, 1.f); }
#pragma unroll
            for (int nt = 0; nt < 4; ++nt) {
                int gn = tile_n + wn + nt * 8 + tig * 2;
                if (gn >= Nout) continue;
                float2 v = make_float2(acc[mt][nt][half * 2], acc[mt][nt][half * 2 + 1]);
                if (MODE == 0) {
                    if (bias) {
                        float2 b = __ldg((const float2*)&bias[gn]);
                        v.x += b.x; v.y += b.y;
                    }
                    *(float2*)&out0[(size_t)gm * Dd + gn] = v;
                } else if (MODE == 3) {
                    float2 b = __ldg((const float2*)&bias[gn]);
                    v.x += b.x; v.y += b.y;
                    if (gn < Dd) {
                        *(float2*)&out0[(size_t)gm * Dd + gn] = v;
                    } else {
                        int gn2 = gn - Dd;
                        float2 a = *(const float2*)&add_src[(size_t)ai * Dd + gn2];
                        v.x = fmaxf(v.x + a.x, 0.f);
                        v.y = fmaxf(v.y + a.y, 0.f);
                        red_v2(&out1[(size_t)si * Dd + gn2], v);
                    }
                } else {  // MODE 5
                    float2 b = __ldg((const float2*)&bias[gn]);
                    float2 a = *(const float2*)&add_src[(size_t)gm * Dd + gn];
                    float2 b2 = make_float2(0.f, 0.f);
                    if (ct > 0.f) b2 = __ldg((const float2*)&bias2[gn]);
                    v.x = fmaxf(v.x * inv + b.x + b2.x + a.x, 0.f);
                    v.y = fmaxf(v.y * inv + b.y + b2.y + a.y, 0.f);
                    *(float2*)&out0[(size_t)gm * Dd + gn] = v;
                }
            }
        }
    }
}

template <int MODE>
__global__ __launch_bounds__(256) void k_gemm_tc(
    int M, int Nout,
    const float* __restrict__ A, const int* __restrict__ aidx,
    const float* __restrict__ W, int ldw,
    const float* __restrict__ bias, const float* __restrict__ bias2,
    float* __restrict__ out0, float* __restrict__ out1,
    const float* __restrict__ add_src, const int* __restrict__ add_idx,
    const int* __restrict__ scat_idx, const float* __restrict__ cntv)
{
    gemm_body<MODE>(M, Nout, A, aidx, W, ldw, bias, bias2, out0, out1,
                    add_src, add_idx, scat_idx, cntv);
}

// batched plain GEMM: blockIdx.z selects (A, W, O)
struct Bat5 { const float* A[5]; const float* W[5]; float* O[5]; };

__global__ __launch_bounds__(256) void k_gemm_bat(int M, int Nout, Bat5 bat, int ldw) {
    int z = blockIdx.z;
    gemm_body<0>(M, Nout, bat.A[z], nullptr, bat.W[z], ldw, nullptr, nullptr,
                 bat.O[z], nullptr, nullptr, nullptr, nullptr, nullptr);
}

// ---------------- gather-sum of 4 pre-transformed tables (float4/thread) -------
__global__ void k_gsum4(const int* __restrict__ tok) {
    int i = blockIdx.x * blockDim.x + threadIdx.x;
    if (i >= Nn * 75) return;
    int n = i / 75, d0 = (i - n * 75) * 4;
    int4 t = ((const int4*)tok)[n];
    size_t o0 = (size_t)t.x * Dd + d0, o1 = (size_t)t.y * Dd + d0;
    size_t o2 = (size_t)t.z * Dd + d0, o3 = (size_t)t.w * Dd + d0;
    size_t di = (size_t)n * Dd + d0;
    float4 r, a0, a1, a2, a3;
    a0 = *(const float4*)&g_embA[o0]; a1 = *(const float4*)&g_embA[o1];
    a2 = *(const float4*)&g_embA[o2]; a3 = *(const float4*)&g_embA[o3];
    r.x = a0.x + a1.x + a2.x + a3.x; r.y = a0.y + a1.y + a2.y + a3.y;
    r.z = a0.z + a1.z + a2.z + a3.z; r.w = a0.w + a1.w + a2.w + a3.w;
    *(float4*)&g_gsA[di] = r;
    a0 = *(const float4*)&g_embB[o0]; a1 = *(const float4*)&g_embB[o1];
    a2 = *(const float4*)&g_embB[o2]; a3 = *(const float4*)&g_embB[o3];
    r.x = a0.x + a1.x + a2.x + a3.x; r.y = a0.y + a1.y + a2.y + a3.y;
    r.z = a0.z + a1.z + a2.z + a3.z; r.w = a0.w + a1.w + a2.w + a3.w;
    *(float4*)&g_gsB[di] = r;
    a0 = *(const float4*)&g_embD[o0]; a1 = *(const float4*)&g_embD[o1];
    a2 = *(const float4*)&g_embD[o2]; a3 = *(const float4*)&g_embD[o3];
    r.x = a0.x + a1.x + a2.x + a3.x; r.y = a0.y + a1.y + a2.y + a3.y;
    r.z = a0.z + a1.z + a2.z + a3.z; r.w = a0.w + a1.w + a2.w + a3.w;
    *(float4*)&g_gsD[di] = r;
    a0 = *(const float4*)&g_embF[o0]; a1 = *(const float4*)&g_embF[o1];
    a2 = *(const float4*)&g_embF[o2]; a3 = *(const float4*)&g_embF[o3];
    r.x = a0.x + a1.x + a2.x + a3.x; r.y = a0.y + a1.y + a2.y + a3.y;
    r.z = a0.z + a1.z + a2.z + a3.z; r.w = a0.w + a1.w + a2.w + a3.w;
    *(float4*)&g_gsF[di] = r;
}

// ---------------- edge layer-1 elementwise (float4/thread, streaming h store) ---
__global__ void k_edge_l1(const int* __restrict__ ea_tok,
                          const int* __restrict__ row, const int* __restrict__ col,
                          const float* __restrict__ eb1) {
    int i = blockIdx.x * blockDim.x + threadIdx.x;
    if (i >= Ee * 75) return;
    int e = i / 75, d0 = (i - e * 75) * 4;
    int4 t = ((const int4*)ea_tok)[e];
    float4 c0 = *(const float4*)&g_embC[(size_t)t.x * Dd + d0];
    float4 c1 = *(const float4*)&g_embC[(size_t)t.y * Dd + d0];
    float4 c2 = *(const float4*)&g_embC[(size_t)t.z * Dd + d0];
    float4 c3 = *(const float4*)&g_embC[(size_t)t.w * Dd + d0];
    int r = __ldg(&row[e]), q = __ldg(&col[e]);
    float sg = g_sign[e];
    float4 ga = *(const float4*)&g_gsA[(size_t)r * Dd + d0];
    float4 gb = *(const float4*)&g_gsB[(size_t)q * Dd + d0];
    float4 bb = __ldg((const float4*)&eb1[d0]);
    float4 o;
    o.x = fmaxf(ga.x + gb.x + (c0.x + c1.x + c2.x + c3.x) * sg + bb.x, 0.f);
    o.y = fmaxf(ga.y + gb.y + (c0.y + c1.y + c2.y + c3.y) * sg + bb.y, 0.f);
    o.z = fmaxf(ga.z + gb.z + (c0.z + c1.z + c2.z + c3.z) * sg + bb.z, 0.f);
    o.w = fmaxf(ga.w + gb.w + (c0.w + c1.w + c2.w + c3.w) * sg + bb.w, 0.f);
    // streaming store: g_h is 4x L2 size; keep embC/gsA/gsB lines resident instead
    __stcs((float4*)&g_h[(size_t)e * Dd + d0], o);
}

// ---------------- merged precompute: wcat + bcat + bb ---------------------------
__global__ void k_prep(const float* __restrict__ ew2, const float* __restrict__ eb2,
                       const float* __restrict__ n1w1, const float* __restrict__ n1b1,
                       const float* __restrict__ n1b2, const float* __restrict__ n2w1) {
    int i = blockIdx.x * blockDim.x + threadIdx.x;
    if (i < Dd * 2 * Dd) {
        int k = i / (2 * Dd), n = i - k * 2 * Dd;
        g_wcat[i] = (n < Dd) ? ew2[(size_t)k * Dd + n] : g_w2p[(size_t)k * Dd + (n - Dd)];
    } else if (i < Dd * 2 * Dd + 2 * Dd) {
        int j = i - Dd * 2 * Dd;
        if (j < Dd) {
            g_bcat[j] = eb2[j];
        } else {
            int n = j - Dd;
            float s = n1b1[n];
            for (int k = 0; k < Dd; k++) s += eb2[k] * n1w1[(size_t)(Dd + k) * Dd + n];
            g_bcat[j] = s;
        }
    } else if (i < Dd * 2 * Dd + 2 * Dd + Dd) {
        int m = i - (Dd * 2 * Dd + 2 * Dd);
        float s = 0.f;
        for (int k = 0; k < Dd; k++) s += n1b2[k] * n2w1[(size_t)(Dd + k) * Dd + m];
        g_bb[m] = s;
    }
}

// ---------------- graph layer norm ----------------------------------------------
__global__ void k_stats(const int* __restrict__ batch) {
    int n = blockIdx.x;
    float s = 0.f, q = 0.f;
    for (int d = threadIdx.x; d < Dd; d += 128) {
        float v = g_xenc[(size_t)n * Dd + d];
        s += v; q += v * v;
    }
#pragma unroll
    for (int o = 16; o; o >>= 1) {
        s += __shfl_down_sync(0xFFFFFFFFu, s, o);
        q += __shfl_down_sync(0xFFFFFFFFu, q, o);
    }
    __shared__ float ss[4], qq[4];
    int w = threadIdx.x >> 5, l = threadIdx.x & 31;
    if (l == 0) { ss[w] = s; qq[w] = q; }
    __syncthreads();
    if (threadIdx.x == 0) {
        s = ss[0] + ss[1] + ss[2] + ss[3];
        q = qq[0] + qq[1] + qq[2] + qq[3];
        int g = batch[n];
        atomicAdd(&g_gsum[g], s);
        atomicAdd(&g_gsq[g], q);
        atomicAdd(&g_gcnt[g], 1.f);
    }
}
__global__ void k_finalize() {
    int g = threadIdx.x;
    if (g < Gg) {
        float denom = fmaxf(g_gcnt[g] * (float)Dd, 1.f);
        float mean = g_gsum[g] / denom;
        float var = g_gsq[g] / denom - mean * mean;
        g_gmean[g] = mean;
        g_grstd[g] = rsqrtf(var + EPSv);
    }
}
__global__ void k_apply(const int* __restrict__ batch,
                        const float* __restrict__ lnw, const float* __restrict__ lnb,
                        float* __restrict__ out) {
    int i = blockIdx.x * blockDim.x + threadIdx.x;
    if (i >= Nn * 75) return;
    int n = i / 75, d0 = (i - n * 75) * 4;
    int g = __ldg(&batch[n]);
    float mean = g_gmean[g], rstd = g_grstd[g];
    float4 x = *(const float4*)&g_xenc[(size_t)n * Dd + d0];
    float4 wv = __ldg((const float4*)&lnw[d0]);
    float4 bv = __ldg((const float4*)&lnb[d0]);
    float4 o;
    o.x = (x.x - mean) * rstd * wv.x + bv.x;
    o.y = (x.y - mean) * rstd * wv.y + bv.y;
    o.z = (x.z - mean) * rstd * wv.z + bv.z;
    o.w = (x.w - mean) * rstd * wv.w + bv.w;
    *(float4*)&out[(size_t)n * Dd + d0] = o;
}

// ---------------- launch ---------------------------------------------------------
static float* symf(const void* s) {
    void* p = nullptr;
    cudaGetSymbolAddress(&p, s);
    return (float*)p;
}

extern "C" void kernel_launch(void* const* d_in, const int* in_sizes, int n_in,
                              void* d_out, int out_size) {
    const int*   x_tok  = (const int*)d_in[0];
    const int*   ea_tok = (const int*)d_in[1];
    const int*   eidx   = (const int*)d_in[2];
    const int*   ase    = (const int*)d_in[3];
    const int*   batch  = (const int*)d_in[4];
    const float* emb    = (const float*)d_in[5];
    const float* ew1  = (const float*)d_in[6];
    const float* eb1  = (const float*)d_in[7];
    const float* ew2  = (const float*)d_in[8];
    const float* eb2  = (const float*)d_in[9];
    const float* n1w1 = (const float*)d_in[10];
    const float* n1b1 = (const float*)d_in[11];
    const float* n1w2 = (const float*)d_in[12];
    const float* n1b2 = (const float*)d_in[13];
    const float* n2w1 = (const float*)d_in[14];
    const float* n2b1 = (const float*)d_in[15];
    const float* n2w2 = (const float*)d_in[16];
    const float* n2b2 = (const float*)d_in[17];
    const float* lnw  = (const float*)d_in[18];
    const float* lnb  = (const float*)d_in[19];

    const int* row = eidx;
    const int* col = eidx + Ee;

    float* out = (float*)d_out;
    float* edge_out = out + (size_t)Nn * Dd;

    float* pembA = symf(g_embA); float* pembB = symf(g_embB);
    float* pembC = symf(g_embC); float* pembD = symf(g_embD);
    float* pembF = symf(g_embF);
    float* pgsD  = symf(g_gsD);  float* pgsF  = symf(g_gsF);
    float* ph    = symf(g_h);
    float* pagg  = symf(g_agg);  float* pxenc = symf(g_xenc);
    float* pw2p  = symf(g_w2p);  float* pw12  = symf(g_w12);
    float* pwcat = symf(g_wcat); float* pbcat = symf(g_bcat);
    float* pcnt  = symf(g_cnt);

    const int T256 = 256;

    // init + sign/cnt
    k_init<<<2048, T256>>>();
    k_signset_cnt<<<(Ee + T256 - 1) / T256, T256>>>(ase, col);

    // batched emb precompute: emb @ {Wa, Wb, Wc, Wd, Wf}
    {
        Bat5 b;
        b.A[0] = emb; b.A[1] = emb; b.A[2] = emb; b.A[3] = emb; b.A[4] = emb;
        b.W[0] = ew1; b.W[1] = ew1 + 300*300; b.W[2] = ew1 + 600*300;
        b.W[3] = n1w1; b.W[4] = n2w1;
        b.O[0] = pembA; b.O[1] = pembB; b.O[2] = pembC; b.O[3] = pembD; b.O[4] = pembF;
        k_gemm_bat<<<dim3(5, (Vv + BMt - 1) / BMt, 5), T256>>>(Vv, Dd, b, Dd);
    }
    // batched small GEMMs: w2p = ew2 @ n1w1_hi ; w12 = n1w2 @ n2w1_hi
    {
        Bat5 b;
        b.A[0] = ew2;  b.A[1] = n1w2; b.A[2] = ew2; b.A[3] = ew2; b.A[4] = ew2;
        b.W[0] = n1w1 + 300*300; b.W[1] = n2w1 + 300*300;
        b.W[2] = b.W[0]; b.W[3] = b.W[0]; b.W[4] = b.W[0];
        b.O[0] = pw2p; b.O[1] = pw12; b.O[2] = pw2p; b.O[3] = pw2p; b.O[4] = pw2p;
        k_gemm_bat<<<dim3(5, (Dd + BMt - 1) / BMt, 2), T256>>>(Dd, Dd, b, Dd);
    }
    // merged wcat + bcat + bb
    k_prep<<<(Dd * 2 * Dd + 3 * Dd + T256 - 1) / T256, T256>>>(ew2, eb2, n1w1, n1b1, n1b2, n2w1);

    // gather-sums + edge layer-1
    k_gsum4<<<(Nn * 75 + T256 - 1) / T256, T256>>>(x_tok);
    k_edge_l1<<<(Ee * 75 + T256 - 1) / T256, T256>>>(ea_tok, row, col, eb1);

    // dual GEMM: edge_enc (store) + h2 (relu + gsD[row]) scattered into aggsum
    k_gemm_tc<3><<<dim3(10, Ee / BMt), T256>>>(Ee, 2 * Dd, ph, nullptr, pwcat, 2 * Dd,
                                               pbcat, nullptr, edge_out, pagg,
                                               pgsD, row, col, nullptr);
    // node2 layer-1: relu(aggsum@W12/cnt + gsF + (cnt>0)bb + n2b1)
    dim3 gN(5, (Nn + BMt - 1) / BMt);
    k_gemm_tc<5><<<gN, T256>>>(Nn, Dd, pagg, nullptr, pw12, Dd, n2b1, symf(g_bb),
                               ph, nullptr, pgsF, nullptr, nullptr, pcnt);
    // node2 layer-2
    k_gemm_tc<0><<<gN, T256>>>(Nn, Dd, ph, nullptr, n2w2, Dd, n2b2, nullptr,
                               pxenc, nullptr, nullptr, nullptr, nullptr, nullptr);

    // graph layer norm
    k_stats<<<Nn, 128>>>(batch);
    k_finalize<<<1, 128>>>();
    k_apply<<<(Nn * 75 + T256 - 1) / T256, T256>>>(batch, lnw, lnb, out);
}

// round 11
// speedup vs baseline: 1.8566x; 1.0304x over previous
#include <cuda_runtime.h>
#include <cstdint>

#define Nn 100000
#define Ee 400000
#define Dd 300
#define Vv 3000
#define Gg 128
#define EPSv 1e-5f
#define WCAT_LD 640

// ---------------- scratch (device globals) ------------------------------------
__device__ __align__(16) float g_embA[(size_t)Vv * Dd];
__device__ __align__(16) float g_embB[(size_t)Vv * Dd];
__device__ __align__(16) float g_embC[(size_t)Vv * Dd];
__device__ __align__(16) float g_embD[(size_t)Vv * Dd];
__device__ __align__(16) float g_embF[(size_t)Vv * Dd];
__device__ __align__(16) float g_gsA [(size_t)Nn * Dd];
__device__ __align__(16) float g_gsB [(size_t)Nn * Dd];
__device__ __align__(16) float g_gsD [(size_t)Nn * Dd];
__device__ __align__(16) float g_gsF [(size_t)Nn * Dd];
__device__ __align__(16) float g_h   [(size_t)Ee * Dd];   // h1; later node2 hidden (first Nn rows)
__device__ __align__(16) float g_agg [(size_t)Nn * Dd];   // aggsum of h2
__device__ __align__(16) float g_xenc[(size_t)Nn * Dd];
__device__ __align__(16) float g_w2p [Dd * Dd];           // ew2 @ n1w1_hi
__device__ __align__(16) float g_w12 [Dd * Dd];           // n1w2 @ n2w1_hi
__device__ __align__(16) float g_wcat[Dd * WCAT_LD];      // [300][640] col-permuted [ew2|w2p|0]
__device__ __align__(16) float g_bcat[2 * Dd];
__device__ __align__(16) float g_bb[Dd];                  // n1b2 @ n2w1_hi
__device__ float g_cnt[Nn];
__device__ float g_sign[Ee];
__device__ float g_gsum[Gg], g_gsq[Gg], g_gcnt[Gg], g_gmean[Gg], g_grstd[Gg];

// ---------------- merged init (float4 stores) -----------------------------------
__global__ void k_init() {
    long long i = (long long)blockIdx.x * blockDim.x + threadIdx.x;
    long long stride = (long long)gridDim.x * blockDim.x;
    float4 z = make_float4(0.f, 0.f, 0.f, 0.f);
    for (long long j = i; j < (long long)Nn * Dd / 4; j += stride)
        ((float4*)g_agg)[j] = z;
    for (long long j = i; j < Nn / 4; j += stride)
        ((float4*)g_cnt)[j] = z;
    for (long long j = i; j < Ee / 4; j += stride)
        ((float4*)g_sign)[j] = make_float4(1.f, 1.f, 1.f, 1.f);
    if (i < Gg) { g_gsum[i] = 0.f; g_gsq[i] = 0.f; g_gcnt[i] = 0.f; }
}
__global__ void k_signset_cnt(const int* __restrict__ ase, const int* __restrict__ col) {
    int i = blockIdx.x * blockDim.x + threadIdx.x;
    if (i < Ee) atomicAdd(&g_cnt[col[i]], 1.f);
    if (i < Ee / 2) g_sign[ase[i]] = -1.f;
}

// ---------------- mma / cp.async / red helpers ---------------------------------
__device__ __forceinline__ void mma_tf32(float* c, unsigned a0, unsigned a1,
                                         unsigned a2, unsigned a3,
                                         unsigned b0, unsigned b1) {
    asm volatile(
        "mma.sync.aligned.m16n8k8.row.col.f32.tf32.tf32.f32 "
        "{%0,%1,%2,%3}, {%4,%5,%6,%7}, {%8,%9}, {%0,%1,%2,%3};"
        : "+f"(c[0]), "+f"(c[1]), "+f"(c[2]), "+f"(c[3])
        : "r"(a0), "r"(a1), "r"(a2), "r"(a3), "r"(b0), "r"(b1));
}
__device__ __forceinline__ void cpa16(unsigned int dst, const void* src, bool p) {
    int sz = p ? 16 : 0;
    asm volatile("cp.async.cg.shared.global [%0], [%1], 16, %2;"
                 :: "r"(dst), "l"(src), "r"(sz));
}
__device__ __forceinline__ void cpa_commit() {
    asm volatile("cp.async.commit_group;");
}
__device__ __forceinline__ void red_v4(float* p, float4 v) {
    asm volatile("red.global.add.v4.f32 [%0], {%1, %2, %3, %4};"
                 :: "l"(p), "f"(v.x), "f"(v.y), "f"(v.z), "f"(v.w) : "memory");
}

// ---------------- tensor-core GEMM body, K fixed = 300 (r8 proven config) -------
// BM=128, BN=64, BK=16, static smem double buffer, warp tile 32x32.
// MODE 0: out0 = v (+bias)
// MODE 3: dual, W column-permuted per 32-block (ldw=640, logical Nout=600):
//         thread holds 8 consecutive logical cols; gn<300 -> float4 store out0;
//         300<=gn<600 -> relu(v+bias+add_src[add_idx[m]]) red.v4 into out1[scat[m]]
// MODE 5: c=cnt[m]; out0 = relu(v/max(c,1) + bias + add_src[m*300+gn] + (c>0?bias2:0))
#define BMt 128
#define BNt 64
#define BKt 16
#define AS_STR 20
#define BS_STR 72
#define NCHUNK 19

template <int MODE>
__device__ __forceinline__ void gemm_body(
    int M, int Nout,
    const float* __restrict__ A, const int* __restrict__ aidx,
    const float* __restrict__ W, int ldw,
    const float* __restrict__ bias, const float* __restrict__ bias2,
    float* __restrict__ out0, float* __restrict__ out1,
    const float* __restrict__ add_src, const int* __restrict__ add_idx,
    const int* __restrict__ scat_idx, const float* __restrict__ cntv)
{
    __shared__ float As[2][BMt * AS_STR];
    __shared__ float Bs[2][BKt * BS_STR];

    const int tid = threadIdx.x;
    const int lane = tid & 31, grp = lane >> 2, tig = lane & 3;
    const int w = tid >> 5;
    const int wm = (w & 3) * 32, wn = (w >> 2) * 32;
    const int tile_n = blockIdx.x * BNt;
    const int tile_m = blockIdx.y * BMt;

    const float* rp[2];
#pragma unroll
    for (int it = 0; it < 2; ++it) {
        int m = (tid >> 2) + it * 64;
        int gm = tile_m + m; if (gm >= M) gm = M - 1;
        int r = aidx ? __ldg(&aidx[gm]) : gm;
        rp[it] = A + (size_t)r * Dd;
    }
    const int ag  = (tid & 3) * 4;
    const int bk  = tid >> 4;
    const int bn4 = (tid & 15) * 4;

    unsigned int sA[2][2], sB[2];
#pragma unroll
    for (int b = 0; b < 2; ++b) {
#pragma unroll
        for (int it = 0; it < 2; ++it) {
            int m = (tid >> 2) + it * 64;
            sA[b][it] = (unsigned int)__cvta_generic_to_shared(&As[b][m * AS_STR + ag]);
        }
        sB[b] = (unsigned int)__cvta_generic_to_shared(&Bs[b][bk * BS_STR + bn4]);
    }

    float acc[2][4][4];
#pragma unroll
    for (int mt = 0; mt < 2; mt++)
#pragma unroll
        for (int nt = 0; nt < 4; nt++)
#pragma unroll
            for (int q = 0; q < 4; q++) acc[mt][nt][q] = 0.f;

    auto load_chunk = [&](int c, int b) {
        int koff = c * BKt;
        int width = 300 - koff; if (width > BKt) width = BKt;
        cpa16(sA[b][0], rp[0] + koff + ag, ag < width);
        cpa16(sA[b][1], rp[1] + koff + ag, ag < width);
        bool pb = (bk < width) && (tile_n + bn4 < Nout);
        cpa16(sB[b], W + (size_t)(koff + bk) * ldw + tile_n + bn4, pb);
    };

    load_chunk(0, 0);
    cpa_commit();

    for (int c = 0; c < NCHUNK; ++c) {
        if (c + 1 < NCHUNK) { load_chunk(c + 1, (c + 1) & 1); cpa_commit(); }
        if (c + 1 < NCHUNK) asm volatile("cp.async.wait_group 1;");
        else                asm volatile("cp.async.wait_group 0;");
        __syncthreads();

        const float* as = As[c & 1];
        const float* bs = Bs[c & 1];
#pragma unroll
        for (int ks = 0; ks < 2; ++ks) {
            const int k0 = ks * 8;
            unsigned af[2][4], bf[4][2];
#pragma unroll
            for (int mt = 0; mt < 2; ++mt) {
                int r0 = (wm + mt * 16 + grp) * AS_STR;
                af[mt][0] = __float_as_uint(as[r0 + k0 + tig]);
                af[mt][1] = __float_as_uint(as[r0 + 8 * AS_STR + k0 + tig]);
                af[mt][2] = __float_as_uint(as[r0 + k0 + tig + 4]);
                af[mt][3] = __float_as_uint(as[r0 + 8 * AS_STR + k0 + tig + 4]);
            }
#pragma unroll
            for (int nt = 0; nt < 4; ++nt) {
                bf[nt][0] = __float_as_uint(bs[(k0 + tig) * BS_STR + wn + nt * 8 + grp]);
                bf[nt][1] = __float_as_uint(bs[(k0 + tig + 4) * BS_STR + wn + nt * 8 + grp]);
            }
#pragma unroll
            for (int mt = 0; mt < 2; ++mt)
#pragma unroll
                for (int nt = 0; nt < 4; ++nt)
                    mma_tf32(acc[mt][nt], af[mt][0], af[mt][1], af[mt][2], af[mt][3],
                             bf[nt][0], bf[nt][1]);
        }
        __syncthreads();
    }

    // ---- epilogue ----
    if (MODE == 3) {
        // permuted-W epilogue: thread covers 8 consecutive LOGICAL cols
        const bool hi_half = (tile_n + wn + 31) >= Dd;
        const int gnb = tile_n + wn + tig * 8;
#pragma unroll
        for (int mt = 0; mt < 2; ++mt) {
#pragma unroll
            for (int half = 0; half < 2; ++half) {
                int gm = tile_m + wm + mt * 16 + grp + half * 8;
                if (gm >= M) continue;
                int ai = 0, si = 0;
                if (hi_half) { ai = __ldg(&add_idx[gm]); si = __ldg(&scat_idx[gm]); }
                const int h2 = half * 2;
#pragma unroll
                for (int g = 0; g < 2; ++g) {
                    int gn = gnb + g * 4;
                    if (gn >= 2 * Dd) continue;
                    float4 v = make_float4(acc[mt][g*2][h2],   acc[mt][g*2][h2+1],
                                           acc[mt][g*2+1][h2], acc[mt][g*2+1][h2+1]);
                    float4 b = __ldg((const float4*)&bias[gn]);
                    v.x += b.x; v.y += b.y; v.z += b.z; v.w += b.w;
                    if (gn < Dd) {
                        *(float4*)&out0[(size_t)gm * Dd + gn] = v;
                    } else {
                        int gn2 = gn - Dd;
                        float4 a = *(const float4*)&add_src[(size_t)ai * Dd + gn2];
                        v.x = fmaxf(v.x + a.x, 0.f);
                        v.y = fmaxf(v.y + a.y, 0.f);
                        v.z = fmaxf(v.z + a.z, 0.f);
                        v.w = fmaxf(v.w + a.w, 0.f);
                        red_v4(&out1[(size_t)si * Dd + gn2], v);
                    }
                }
            }
        }
    } else {
#pragma unroll
        for (int mt = 0; mt < 2; ++mt) {
#pragma unroll
            for (int half = 0; half < 2; ++half) {
                int gm = tile_m + wm + mt * 16 + grp + half * 8;
                if (gm >= M) continue;
                float ct = 0.f, inv = 0.f;
                if (MODE == 5) { ct = __ldg(&cntv[gm]); inv = 1.f / fmaxf(ct, 1.f); }
#pragma unroll
                for (int nt = 0; nt < 4; ++nt) {
                    int gn = tile_n + wn + nt * 8 + tig * 2;
                    if (gn >= Nout) continue;
                    float2 v = make_float2(acc[mt][nt][half * 2], acc[mt][nt][half * 2 + 1]);
                    if (MODE == 0) {
                        if (bias) {
                            float2 b = __ldg((const float2*)&bias[gn]);
                            v.x += b.x; v.y += b.y;
                        }
                        *(float2*)&out0[(size_t)gm * Dd + gn] = v;
                    } else {  // MODE 5
                        float2 b = __ldg((const float2*)&bias[gn]);
                        float2 a = *(const float2*)&add_src[(size_t)gm * Dd + gn];
                        float2 b2 = make_float2(0.f, 0.f);
                        if (ct > 0.f) b2 = __ldg((const float2*)&bias2[gn]);
                        v.x = fmaxf(v.x * inv + b.x + b2.x + a.x, 0.f);
                        v.y = fmaxf(v.y * inv + b.y + b2.y + a.y, 0.f);
                        *(float2*)&out0[(size_t)gm * Dd + gn] = v;
                    }
                }
            }
        }
    }
}

template <int MODE>
__global__ __launch_bounds__(256) void k_gemm_tc(
    int M, int Nout,
    const float* __restrict__ A, const int* __restrict__ aidx,
    const float* __restrict__ W, int ldw,
    const float* __restrict__ bias, const float* __restrict__ bias2,
    float* __restrict__ out0, float* __restrict__ out1,
    const float* __restrict__ add_src, const int* __restrict__ add_idx,
    const int* __restrict__ scat_idx, const float* __restrict__ cntv)
{
    gemm_body<MODE>(M, Nout, A, aidx, W, ldw, bias, bias2, out0, out1,
                    add_src, add_idx, scat_idx, cntv);
}

// batched plain GEMM: blockIdx.z selects (A, W, O)
struct Bat5 { const float* A[5]; const float* W[5]; float* O[5]; };

__global__ __launch_bounds__(256) void k_gemm_bat(int M, int Nout, Bat5 bat, int ldw) {
    int z = blockIdx.z;
    gemm_body<0>(M, Nout, bat.A[z], nullptr, bat.W[z], ldw, nullptr, nullptr,
                 bat.O[z], nullptr, nullptr, nullptr, nullptr, nullptr);
}

// ---------------- gather-sum of 4 pre-transformed tables (float4/thread) -------
__global__ void k_gsum4(const int* __restrict__ tok) {
    int i = blockIdx.x * blockDim.x + threadIdx.x;
    if (i >= Nn * 75) return;
    int n = i / 75, d0 = (i - n * 75) * 4;
    int4 t = ((const int4*)tok)[n];
    size_t o0 = (size_t)t.x * Dd + d0, o1 = (size_t)t.y * Dd + d0;
    size_t o2 = (size_t)t.z * Dd + d0, o3 = (size_t)t.w * Dd + d0;
    size_t di = (size_t)n * Dd + d0;
    float4 r, a0, a1, a2, a3;
    a0 = *(const float4*)&g_embA[o0]; a1 = *(const float4*)&g_embA[o1];
    a2 = *(const float4*)&g_embA[o2]; a3 = *(const float4*)&g_embA[o3];
    r.x = a0.x + a1.x + a2.x + a3.x; r.y = a0.y + a1.y + a2.y + a3.y;
    r.z = a0.z + a1.z + a2.z + a3.z; r.w = a0.w + a1.w + a2.w + a3.w;
    *(float4*)&g_gsA[di] = r;
    a0 = *(const float4*)&g_embB[o0]; a1 = *(const float4*)&g_embB[o1];
    a2 = *(const float4*)&g_embB[o2]; a3 = *(const float4*)&g_embB[o3];
    r.x = a0.x + a1.x + a2.x + a3.x; r.y = a0.y + a1.y + a2.y + a3.y;
    r.z = a0.z + a1.z + a2.z + a3.z; r.w = a0.w + a1.w + a2.w + a3.w;
    *(float4*)&g_gsB[di] = r;
    a0 = *(const float4*)&g_embD[o0]; a1 = *(const float4*)&g_embD[o1];
    a2 = *(const float4*)&g_embD[o2]; a3 = *(const float4*)&g_embD[o3];
    r.x = a0.x + a1.x + a2.x + a3.x; r.y = a0.y + a1.y + a2.y + a3.y;
    r.z = a0.z + a1.z + a2.z + a3.z; r.w = a0.w + a1.w + a2.w + a3.w;
    *(float4*)&g_gsD[di] = r;
    a0 = *(const float4*)&g_embF[o0]; a1 = *(const float4*)&g_embF[o1];
    a2 = *(const float4*)&g_embF[o2]; a3 = *(const float4*)&g_embF[o3];
    r.x = a0.x + a1.x + a2.x + a3.x; r.y = a0.y + a1.y + a2.y + a3.y;
    r.z = a0.z + a1.z + a2.z + a3.z; r.w = a0.w + a1.w + a2.w + a3.w;
    *(float4*)&g_gsF[di] = r;
}

// ---------------- edge layer-1 elementwise (float4/thread, streaming h store) ---
__global__ void k_edge_l1(const int* __restrict__ ea_tok,
                          const int* __restrict__ row, const int* __restrict__ col,
                          const float* __restrict__ eb1) {
    int i = blockIdx.x * blockDim.x + threadIdx.x;
    if (i >= Ee * 75) return;
    int e = i / 75, d0 = (i - e * 75) * 4;
    int4 t = ((const int4*)ea_tok)[e];
    float4 c0 = *(const float4*)&g_embC[(size_t)t.x * Dd + d0];
    float4 c1 = *(const float4*)&g_embC[(size_t)t.y * Dd + d0];
    float4 c2 = *(const float4*)&g_embC[(size_t)t.z * Dd + d0];
    float4 c3 = *(const float4*)&g_embC[(size_t)t.w * Dd + d0];
    int r = __ldg(&row[e]), q = __ldg(&col[e]);
    float sg = g_sign[e];
    float4 ga = *(const float4*)&g_gsA[(size_t)r * Dd + d0];
    float4 gb = *(const float4*)&g_gsB[(size_t)q * Dd + d0];
    float4 bb = __ldg((const float4*)&eb1[d0]);
    float4 o;
    o.x = fmaxf(ga.x + gb.x + (c0.x + c1.x + c2.x + c3.x) * sg + bb.x, 0.f);
    o.y = fmaxf(ga.y + gb.y + (c0.y + c1.y + c2.y + c3.y) * sg + bb.y, 0.f);
    o.z = fmaxf(ga.z + gb.z + (c0.z + c1.z + c2.z + c3.z) * sg + bb.z, 0.f);
    o.w = fmaxf(ga.w + gb.w + (c0.w + c1.w + c2.w + c3.w) * sg + bb.w, 0.f);
    __stcs((float4*)&g_h[(size_t)e * Dd + d0], o);
}

// ---------------- merged precompute: permuted wcat + bcat + bb ------------------
__global__ void k_prep(const float* __restrict__ ew2, const float* __restrict__ eb2,
                       const float* __restrict__ n1w1, const float* __restrict__ n1b1,
                       const float* __restrict__ n1b2, const float* __restrict__ n2w1) {
    int i = blockIdx.x * blockDim.x + threadIdx.x;
    if (i < Dd * WCAT_LD) {
        int k = i / WCAT_LD, p = i - k * WCAT_LD;
        int j = p & 31;
        int f = ((j >> 1) & 3) * 8 + ((j >> 3) & 3) * 2 + (j & 1);  // nt<->tig swap
        int lp = (p & ~31) | f;
        float v = 0.f;
        if (lp < Dd)            v = ew2[(size_t)k * Dd + lp];
        else if (lp < 2 * Dd)   v = g_w2p[(size_t)k * Dd + (lp - Dd)];
        g_wcat[i] = v;
    } else if (i < Dd * WCAT_LD + 2 * Dd) {
        int j = i - Dd * WCAT_LD;
        if (j < Dd) {
            g_bcat[j] = eb2[j];
        } else {
            int n = j - Dd;
            float s = n1b1[n];
            for (int k = 0; k < Dd; k++) s += eb2[k] * n1w1[(size_t)(Dd + k) * Dd + n];
            g_bcat[j] = s;
        }
    } else if (i < Dd * WCAT_LD + 2 * Dd + Dd) {
        int m = i - (Dd * WCAT_LD + 2 * Dd);
        float s = 0.f;
        for (int k = 0; k < Dd; k++) s += n1b2[k] * n2w1[(size_t)(Dd + k) * Dd + m];
        g_bb[m] = s;
    }
}

// ---------------- graph layer norm ----------------------------------------------
__global__ void k_stats(const int* __restrict__ batch) {
    int n = blockIdx.x;
    float s = 0.f, q = 0.f;
    for (int d = threadIdx.x; d < Dd; d += 128) {
        float v = g_xenc[(size_t)n * Dd + d];
        s += v; q += v * v;
    }
#pragma unroll
    for (int o = 16; o; o >>= 1) {
        s += __shfl_down_sync(0xFFFFFFFFu, s, o);
        q += __shfl_down_sync(0xFFFFFFFFu, q, o);
    }
    __shared__ float ss[4], qq[4];
    int w = threadIdx.x >> 5, l = threadIdx.x & 31;
    if (l == 0) { ss[w] = s; qq[w] = q; }
    __syncthreads();
    if (threadIdx.x == 0) {
        s = ss[0] + ss[1] + ss[2] + ss[3];
        q = qq[0] + qq[1] + qq[2] + qq[3];
        int g = batch[n];
        atomicAdd(&g_gsum[g], s);
        atomicAdd(&g_gsq[g], q);
        atomicAdd(&g_gcnt[g], 1.f);
    }
}
__global__ void k_finalize() {
    int g = threadIdx.x;
    if (g < Gg) {
        float denom = fmaxf(g_gcnt[g] * (float)Dd, 1.f);
        float mean = g_gsum[g] / denom;
        float var = g_gsq[g] / denom - mean * mean;
        g_gmean[g] = mean;
        g_grstd[g] = rsqrtf(var + EPSv);
    }
}
__global__ void k_apply(const int* __restrict__ batch,
                        const float* __restrict__ lnw, const float* __restrict__ lnb,
                        float* __restrict__ out) {
    int i = blockIdx.x * blockDim.x + threadIdx.x;
    if (i >= Nn * 75) return;
    int n = i / 75, d0 = (i - n * 75) * 4;
    int g = __ldg(&batch[n]);
    float mean = g_gmean[g], rstd = g_grstd[g];
    float4 x = *(const float4*)&g_xenc[(size_t)n * Dd + d0];
    float4 wv = __ldg((const float4*)&lnw[d0]);
    float4 bv = __ldg((const float4*)&lnb[d0]);
    float4 o;
    o.x = (x.x - mean) * rstd * wv.x + bv.x;
    o.y = (x.y - mean) * rstd * wv.y + bv.y;
    o.z = (x.z - mean) * rstd * wv.z + bv.z;
    o.w = (x.w - mean) * rstd * wv.w + bv.w;
    *(float4*)&out[(size_t)n * Dd + d0] = o;
}

// ---------------- launch ---------------------------------------------------------
static float* symf(const void* s) {
    void* p = nullptr;
    cudaGetSymbolAddress(&p, s);
    return (float*)p;
}

extern "C" void kernel_launch(void* const* d_in, const int* in_sizes, int n_in,
                              void* d_out, int out_size) {
    const int*   x_tok  = (const int*)d_in[0];
    const int*   ea_tok = (const int*)d_in[1];
    const int*   eidx   = (const int*)d_in[2];
    const int*   ase    = (const int*)d_in[3];
    const int*   batch  = (const int*)d_in[4];
    const float* emb    = (const float*)d_in[5];
    const float* ew1  = (const float*)d_in[6];
    const float* eb1  = (const float*)d_in[7];
    const float* ew2  = (const float*)d_in[8];
    const float* eb2  = (const float*)d_in[9];
    const float* n1w1 = (const float*)d_in[10];
    const float* n1b1 = (const float*)d_in[11];
    const float* n1w2 = (const float*)d_in[12];
    const float* n1b2 = (const float*)d_in[13];
    const float* n2w1 = (const float*)d_in[14];
    const float* n2b1 = (const float*)d_in[15];
    const float* n2w2 = (const float*)d_in[16];
    const float* n2b2 = (const float*)d_in[17];
    const float* lnw  = (const float*)d_in[18];
    const float* lnb  = (const float*)d_in[19];

    const int* row = eidx;
    const int* col = eidx + Ee;

    float* out = (float*)d_out;
    float* edge_out = out + (size_t)Nn * Dd;

    float* pembA = symf(g_embA); float* pembB = symf(g_embB);
    float* pembC = symf(g_embC); float* pembD = symf(g_embD);
    float* pembF = symf(g_embF);
    float* pgsD  = symf(g_gsD);  float* pgsF  = symf(g_gsF);
    float* ph    = symf(g_h);
    float* pagg  = symf(g_agg);  float* pxenc = symf(g_xenc);
    float* pw2p  = symf(g_w2p);  float* pw12  = symf(g_w12);
    float* pwcat = symf(g_wcat); float* pbcat = symf(g_bcat);
    float* pcnt  = symf(g_cnt);

    const int T256 = 256;

    // init + sign/cnt
    k_init<<<2048, T256>>>();
    k_signset_cnt<<<(Ee + T256 - 1) / T256, T256>>>(ase, col);

    // batched emb precompute: emb @ {Wa, Wb, Wc, Wd, Wf}
    {
        Bat5 b;
        b.A[0] = emb; b.A[1] = emb; b.A[2] = emb; b.A[3] = emb; b.A[4] = emb;
        b.W[0] = ew1; b.W[1] = ew1 + 300*300; b.W[2] = ew1 + 600*300;
        b.W[3] = n1w1; b.W[4] = n2w1;
        b.O[0] = pembA; b.O[1] = pembB; b.O[2] = pembC; b.O[3] = pembD; b.O[4] = pembF;
        k_gemm_bat<<<dim3(5, (Vv + BMt - 1) / BMt, 5), T256>>>(Vv, Dd, b, Dd);
    }
    // batched small GEMMs: w2p = ew2 @ n1w1_hi ; w12 = n1w2 @ n2w1_hi
    {
        Bat5 b;
        b.A[0] = ew2;  b.A[1] = n1w2; b.A[2] = ew2; b.A[3] = ew2; b.A[4] = ew2;
        b.W[0] = n1w1 + 300*300; b.W[1] = n2w1 + 300*300;
        b.W[2] = b.W[0]; b.W[3] = b.W[0]; b.W[4] = b.W[0];
        b.O[0] = pw2p; b.O[1] = pw12; b.O[2] = pw2p; b.O[3] = pw2p; b.O[4] = pw2p;
        k_gemm_bat<<<dim3(5, (Dd + BMt - 1) / BMt, 2), T256>>>(Dd, Dd, b, Dd);
    }
    // merged permuted wcat + bcat + bb
    k_prep<<<(Dd * WCAT_LD + 3 * Dd + T256 - 1) / T256, T256>>>(ew2, eb2, n1w1, n1b1, n1b2, n2w1);

    // gather-sums + edge layer-1
    k_gsum4<<<(Nn * 75 + T256 - 1) / T256, T256>>>(x_tok);
    k_edge_l1<<<(Ee * 75 + T256 - 1) / T256, T256>>>(ea_tok, row, col, eb1);

    // dual GEMM (permuted W, ldw=640): edge_enc (float4 store) + h2 (red.v4 scatter)
    k_gemm_tc<3><<<dim3(10, Ee / BMt), T256>>>(Ee, WCAT_LD, ph, nullptr, pwcat, WCAT_LD,
                                               pbcat, nullptr, edge_out, pagg,
                                               pgsD, row, col, nullptr);
    // node2 layer-1: relu(aggsum@W12/cnt + gsF + (cnt>0)bb + n2b1)
    dim3 gN(5, (Nn + BMt - 1) / BMt);
    k_gemm_tc<5><<<gN, T256>>>(Nn, Dd, pagg, nullptr, pw12, Dd, n2b1, symf(g_bb),
                               ph, nullptr, pgsF, nullptr, nullptr, pcnt);
    // node2 layer-2
    k_gemm_tc<0><<<gN, T256>>>(Nn, Dd, ph, nullptr, n2w2, Dd, n2b2, nullptr,
                               pxenc, nullptr, nullptr, nullptr, nullptr, nullptr);

    // graph layer norm
    k_stats<<<Nn, 128>>>(batch);
    k_finalize<<<1, 128>>>();
    k_apply<<<(Nn * 75 + T256 - 1) / T256, T256>>>(batch, lnw, lnb, out);
}

// round 12
// speedup vs baseline: 1.8634x; 1.0037x over previous
#include <cuda_runtime.h>
#include <cstdint>

#define Nn 100000
#define Ee 400000
#define Dd 300
#define Vv 3000
#define Gg 128
#define EPSv 1e-5f
#define WCAT_LD 640
#define WP_LD 320

// ---------------- scratch (device globals) ------------------------------------
__device__ __align__(16) float g_embA[(size_t)Vv * Dd];
__device__ __align__(16) float g_embB[(size_t)Vv * Dd];
__device__ __align__(16) float g_embC[(size_t)Vv * Dd];
__device__ __align__(16) float g_embD[(size_t)Vv * Dd];
__device__ __align__(16) float g_embF[(size_t)Vv * Dd];
__device__ __align__(16) float g_gsA [(size_t)Nn * Dd];
__device__ __align__(16) float g_gsB [(size_t)Nn * Dd];
__device__ __align__(16) float g_gsD [(size_t)Nn * Dd];
__device__ __align__(16) float g_gsF [(size_t)Nn * Dd];
__device__ __align__(16) float g_h   [(size_t)Ee * Dd];
__device__ __align__(16) float g_agg [(size_t)Nn * Dd];
__device__ __align__(16) float g_xenc[(size_t)Nn * Dd];
__device__ __align__(16) float g_w2p [Dd * Dd];           // ew2 @ n1w1_hi
__device__ __align__(16) float g_w12 [Dd * Dd];           // n1w2 @ n2w1_hi
__device__ __align__(16) float g_wcat[Dd * WCAT_LD];      // [300][640] permuted [ew2|w2p|0]
__device__ __align__(16) float g_w12p[Dd * WP_LD];        // w12 permuted [300][320]
__device__ __align__(16) float g_wn2p[Dd * WP_LD];        // n2w2 permuted [300][320]
__device__ __align__(16) float g_bcat[2 * Dd];
__device__ __align__(16) float g_bb[Dd];                  // n1b2 @ n2w1_hi (ct>0 gated)
__device__ float g_cnt[Nn];
__device__ float g_sign[Ee];
__device__ float g_gsum[Gg], g_gsq[Gg], g_gcnt[Gg], g_gmean[Gg], g_grstd[Gg];

// ---------------- merged init (float4 stores) -----------------------------------
__global__ void k_init() {
    long long i = (long long)blockIdx.x * blockDim.x + threadIdx.x;
    long long stride = (long long)gridDim.x * blockDim.x;
    float4 z = make_float4(0.f, 0.f, 0.f, 0.f);
    for (long long j = i; j < (long long)Nn * Dd / 4; j += stride)
        ((float4*)g_agg)[j] = z;
    for (long long j = i; j < Nn / 4; j += stride)
        ((float4*)g_cnt)[j] = z;
    for (long long j = i; j < Ee / 4; j += stride)
        ((float4*)g_sign)[j] = make_float4(1.f, 1.f, 1.f, 1.f);
    if (i < Gg) { g_gsum[i] = 0.f; g_gsq[i] = 0.f; g_gcnt[i] = 0.f; }
}
__global__ void k_signset_cnt(const int* __restrict__ ase, const int* __restrict__ col) {
    int i = blockIdx.x * blockDim.x + threadIdx.x;
    if (i < Ee) atomicAdd(&g_cnt[col[i]], 1.f);
    if (i < Ee / 2) g_sign[ase[i]] = -1.f;
}

// ---------------- mma / cp.async / red helpers ---------------------------------
__device__ __forceinline__ void mma_tf32(float* c, unsigned a0, unsigned a1,
                                         unsigned a2, unsigned a3,
                                         unsigned b0, unsigned b1) {
    asm volatile(
        "mma.sync.aligned.m16n8k8.row.col.f32.tf32.tf32.f32 "
        "{%0,%1,%2,%3}, {%4,%5,%6,%7}, {%8,%9}, {%0,%1,%2,%3};"
        : "+f"(c[0]), "+f"(c[1]), "+f"(c[2]), "+f"(c[3])
        : "r"(a0), "r"(a1), "r"(a2), "r"(a3), "r"(b0), "r"(b1));
}
__device__ __forceinline__ void cpa16(unsigned int dst, const void* src, bool p) {
    int sz = p ? 16 : 0;
    asm volatile("cp.async.cg.shared.global [%0], [%1], 16, %2;"
                 :: "r"(dst), "l"(src), "r"(sz));
}
__device__ __forceinline__ void cpa_commit() {
    asm volatile("cp.async.commit_group;");
}
__device__ __forceinline__ void red_v4(float* p, float4 v) {
    asm volatile("red.global.add.v4.f32 [%0], {%1, %2, %3, %4};"
                 :: "l"(p), "f"(v.x), "f"(v.y), "f"(v.z), "f"(v.w) : "memory");
}

// ---------------- tensor-core GEMM body, K fixed = 300 --------------------------
// MODE 0: unpermuted, out0 = v (+bias)                    (precompute path)
// MODE 1: permuted, out0 = v + bias (float4)              (node2-l2)
// MODE 3: permuted dual: gn<300 store; else relu+red.v4   (edge/scatter)
// MODE 6: permuted node2-l1: out0 = relu(v/max(c,1) + bias + add_src + (c>0)bias2)
//         bias added POST-scale (unconditional n2b1), bias2 gated (bb).
#define BMt 128
#define BNt 64
#define BKt 16
#define AS_STR 20
#define BS_STR 72
#define NCHUNK 19

template <int MODE>
__device__ __forceinline__ void gemm_body(
    int M, int Nout,
    const float* __restrict__ A, const int* __restrict__ aidx,
    const float* __restrict__ W, int ldw,
    const float* __restrict__ bias, const float* __restrict__ bias2,
    float* __restrict__ out0, float* __restrict__ out1,
    const float* __restrict__ add_src, const int* __restrict__ add_idx,
    const int* __restrict__ scat_idx, const float* __restrict__ cntv)
{
    __shared__ float As[2][BMt * AS_STR];
    __shared__ float Bs[2][BKt * BS_STR];

    const int tid = threadIdx.x;
    const int lane = tid & 31, grp = lane >> 2, tig = lane & 3;
    const int w = tid >> 5;
    const int wm = (w & 3) * 32, wn = (w >> 2) * 32;
    const int tile_n = blockIdx.x * BNt;
    const int tile_m = blockIdx.y * BMt;

    const float* rp[2];
#pragma unroll
    for (int it = 0; it < 2; ++it) {
        int m = (tid >> 2) + it * 64;
        int gm = tile_m + m; if (gm >= M) gm = M - 1;
        int r = aidx ? __ldg(&aidx[gm]) : gm;
        rp[it] = A + (size_t)r * Dd;
    }
    const int ag  = (tid & 3) * 4;
    const int bk  = tid >> 4;
    const int bn4 = (tid & 15) * 4;

    unsigned int sA[2][2], sB[2];
#pragma unroll
    for (int b = 0; b < 2; ++b) {
#pragma unroll
        for (int it = 0; it < 2; ++it) {
            int m = (tid >> 2) + it * 64;
            sA[b][it] = (unsigned int)__cvta_generic_to_shared(&As[b][m * AS_STR + ag]);
        }
        sB[b] = (unsigned int)__cvta_generic_to_shared(&Bs[b][bk * BS_STR + bn4]);
    }

    float acc[2][4][4];
#pragma unroll
    for (int mt = 0; mt < 2; mt++)
#pragma unroll
        for (int nt = 0; nt < 4; nt++)
#pragma unroll
            for (int q = 0; q < 4; q++) acc[mt][nt][q] = 0.f;

    auto load_chunk = [&](int c, int b) {
        int koff = c * BKt;
        int width = 300 - koff; if (width > BKt) width = BKt;
        cpa16(sA[b][0], rp[0] + koff + ag, ag < width);
        cpa16(sA[b][1], rp[1] + koff + ag, ag < width);
        bool pb = (bk < width) && (tile_n + bn4 < Nout);
        cpa16(sB[b], W + (size_t)(koff + bk) * ldw + tile_n + bn4, pb);
    };

    load_chunk(0, 0);
    cpa_commit();

    for (int c = 0; c < NCHUNK; ++c) {
        if (c + 1 < NCHUNK) { load_chunk(c + 1, (c + 1) & 1); cpa_commit(); }
        if (c + 1 < NCHUNK) asm volatile("cp.async.wait_group 1;");
        else                asm volatile("cp.async.wait_group 0;");
        __syncthreads();

        const float* as = As[c & 1];
        const float* bs = Bs[c & 1];
#pragma unroll
        for (int ks = 0; ks < 2; ++ks) {
            const int k0 = ks * 8;
            unsigned af[2][4], bf[4][2];
#pragma unroll
            for (int mt = 0; mt < 2; ++mt) {
                int r0 = (wm + mt * 16 + grp) * AS_STR;
                af[mt][0] = __float_as_uint(as[r0 + k0 + tig]);
                af[mt][1] = __float_as_uint(as[r0 + 8 * AS_STR + k0 + tig]);
                af[mt][2] = __float_as_uint(as[r0 + k0 + tig + 4]);
                af[mt][3] = __float_as_uint(as[r0 + 8 * AS_STR + k0 + tig + 4]);
            }
#pragma unroll
            for (int nt = 0; nt < 4; ++nt) {
                bf[nt][0] = __float_as_uint(bs[(k0 + tig) * BS_STR + wn + nt * 8 + grp]);
                bf[nt][1] = __float_as_uint(bs[(k0 + tig + 4) * BS_STR + wn + nt * 8 + grp]);
            }
#pragma unroll
            for (int mt = 0; mt < 2; ++mt)
#pragma unroll
                for (int nt = 0; nt < 4; ++nt)
                    mma_tf32(acc[mt][nt], af[mt][0], af[mt][1], af[mt][2], af[mt][3],
                             bf[nt][0], bf[nt][1]);
        }
        __syncthreads();
    }

    // ---- epilogue ----
    if (MODE == 1 || MODE == 3 || MODE == 6) {
        const bool hi_half = (MODE == 3) && ((tile_n + wn + 31) >= Dd);
        const int gnb = tile_n + wn + tig * 8;
        const int NL = (MODE == 3) ? 2 * Dd : Dd;
#pragma unroll
        for (int mt = 0; mt < 2; ++mt) {
#pragma unroll
            for (int half = 0; half < 2; ++half) {
                int gm = tile_m + wm + mt * 16 + grp + half * 8;
                if (gm >= M) continue;
                int ai = 0, si = 0;
                float ct = 0.f, inv = 0.f;
                if (MODE == 3) {
                    if (hi_half) { ai = __ldg(&add_idx[gm]); si = __ldg(&scat_idx[gm]); }
                }
                if (MODE == 6) { ct = __ldg(&cntv[gm]); inv = 1.f / fmaxf(ct, 1.f); }
                const int h2 = half * 2;
#pragma unroll
                for (int g = 0; g < 2; ++g) {
                    int gn = gnb + g * 4;
                    if (gn >= NL) continue;
                    float4 v = make_float4(acc[mt][g*2][h2],   acc[mt][g*2][h2+1],
                                           acc[mt][g*2+1][h2], acc[mt][g*2+1][h2+1]);
                    float4 b = __ldg((const float4*)&bias[gn]);
                    if (MODE == 1) {
                        v.x += b.x; v.y += b.y; v.z += b.z; v.w += b.w;
                        *(float4*)&out0[(size_t)gm * Dd + gn] = v;
                    } else if (MODE == 3) {
                        v.x += b.x; v.y += b.y; v.z += b.z; v.w += b.w;
                        if (gn < Dd) {
                            *(float4*)&out0[(size_t)gm * Dd + gn] = v;
                        } else {
                            int gn2 = gn - Dd;
                            float4 a = *(const float4*)&add_src[(size_t)ai * Dd + gn2];
                            v.x = fmaxf(v.x + a.x, 0.f);
                            v.y = fmaxf(v.y + a.y, 0.f);
                            v.z = fmaxf(v.z + a.z, 0.f);
                            v.w = fmaxf(v.w + a.w, 0.f);
                            red_v4(&out1[(size_t)si * Dd + gn2], v);
                        }
                    } else {  // MODE 6: v/max(c,1) + n2b1 + gsF + (c>0)bb
                        float4 a = *(const float4*)&add_src[(size_t)gm * Dd + gn];
                        float4 b2 = make_float4(0.f, 0.f, 0.f, 0.f);
                        if (ct > 0.f) b2 = __ldg((const float4*)&bias2[gn]);
                        v.x = fmaxf(v.x * inv + b.x + b2.x + a.x, 0.f);
                        v.y = fmaxf(v.y * inv + b.y + b2.y + a.y, 0.f);
                        v.z = fmaxf(v.z * inv + b.z + b2.z + a.z, 0.f);
                        v.w = fmaxf(v.w * inv + b.w + b2.w + a.w, 0.f);
                        *(float4*)&out0[(size_t)gm * Dd + gn] = v;
                    }
                }
            }
        }
    } else {  // MODE 0
#pragma unroll
        for (int mt = 0; mt < 2; ++mt) {
#pragma unroll
            for (int half = 0; half < 2; ++half) {
                int gm = tile_m + wm + mt * 16 + grp + half * 8;
                if (gm >= M) continue;
#pragma unroll
                for (int nt = 0; nt < 4; ++nt) {
                    int gn = tile_n + wn + nt * 8 + tig * 2;
                    if (gn >= Nout) continue;
                    float2 v = make_float2(acc[mt][nt][half * 2], acc[mt][nt][half * 2 + 1]);
                    if (bias) {
                        float2 b = __ldg((const float2*)&bias[gn]);
                        v.x += b.x; v.y += b.y;
                    }
                    *(float2*)&out0[(size_t)gm * Dd + gn] = v;
                }
            }
        }
    }
}

template <int MODE>
__global__ __launch_bounds__(256) void k_gemm_tc(
    int M, int Nout,
    const float* __restrict__ A, const int* __restrict__ aidx,
    const float* __restrict__ W, int ldw,
    const float* __restrict__ bias, const float* __restrict__ bias2,
    float* __restrict__ out0, float* __restrict__ out1,
    const float* __restrict__ add_src, const int* __restrict__ add_idx,
    const int* __restrict__ scat_idx, const float* __restrict__ cntv)
{
    gemm_body<MODE>(M, Nout, A, aidx, W, ldw, bias, bias2, out0, out1,
                    add_src, add_idx, scat_idx, cntv);
}

struct Bat5 { const float* A[5]; const float* W[5]; float* O[5]; };

__global__ __launch_bounds__(256) void k_gemm_bat(int M, int Nout, Bat5 bat, int ldw) {
    int z = blockIdx.z;
    gemm_body<0>(M, Nout, bat.A[z], nullptr, bat.W[z], ldw, nullptr, nullptr,
                 bat.O[z], nullptr, nullptr, nullptr, nullptr, nullptr);
}

// ---------------- gather-sum of 4 pre-transformed tables (float4/thread) -------
__global__ void k_gsum4(const int* __restrict__ tok) {
    int i = blockIdx.x * blockDim.x + threadIdx.x;
    if (i >= Nn * 75) return;
    int n = i / 75, d0 = (i - n * 75) * 4;
    int4 t = ((const int4*)tok)[n];
    size_t o0 = (size_t)t.x * Dd + d0, o1 = (size_t)t.y * Dd + d0;
    size_t o2 = (size_t)t.z * Dd + d0, o3 = (size_t)t.w * Dd + d0;
    size_t di = (size_t)n * Dd + d0;
    float4 r, a0, a1, a2, a3;
    a0 = *(const float4*)&g_embA[o0]; a1 = *(const float4*)&g_embA[o1];
    a2 = *(const float4*)&g_embA[o2]; a3 = *(const float4*)&g_embA[o3];
    r.x = a0.x + a1.x + a2.x + a3.x; r.y = a0.y + a1.y + a2.y + a3.y;
    r.z = a0.z + a1.z + a2.z + a3.z; r.w = a0.w + a1.w + a2.w + a3.w;
    *(float4*)&g_gsA[di] = r;
    a0 = *(const float4*)&g_embB[o0]; a1 = *(const float4*)&g_embB[o1];
    a2 = *(const float4*)&g_embB[o2]; a3 = *(const float4*)&g_embB[o3];
    r.x = a0.x + a1.x + a2.x + a3.x; r.y = a0.y + a1.y + a2.y + a3.y;
    r.z = a0.z + a1.z + a2.z + a3.z; r.w = a0.w + a1.w + a2.w + a3.w;
    *(float4*)&g_gsB[di] = r;
    a0 = *(const float4*)&g_embD[o0]; a1 = *(const float4*)&g_embD[o1];
    a2 = *(const float4*)&g_embD[o2]; a3 = *(const float4*)&g_embD[o3];
    r.x = a0.x + a1.x + a2.x + a3.x; r.y = a0.y + a1.y + a2.y + a3.y;
    r.z = a0.z + a1.z + a2.z + a3.z; r.w = a0.w + a1.w + a2.w + a3.w;
    *(float4*)&g_gsD[di] = r;
    a0 = *(const float4*)&g_embF[o0]; a1 = *(const float4*)&g_embF[o1];
    a2 = *(const float4*)&g_embF[o2]; a3 = *(const float4*)&g_embF[o3];
    r.x = a0.x + a1.x + a2.x + a3.x; r.y = a0.y + a1.y + a2.y + a3.y;
    r.z = a0.z + a1.z + a2.z + a3.z; r.w = a0.w + a1.w + a2.w + a3.w;
    *(float4*)&g_gsF[di] = r;
}

// ---------------- edge layer-1 elementwise ---------------------------------------
__global__ void k_edge_l1(const int* __restrict__ ea_tok,
                          const int* __restrict__ row, const int* __restrict__ col,
                          const float* __restrict__ eb1) {
    int i = blockIdx.x * blockDim.x + threadIdx.x;
    if (i >= Ee * 75) return;
    int e = i / 75, d0 = (i - e * 75) * 4;
    int4 t = ((const int4*)ea_tok)[e];
    float4 c0 = *(const float4*)&g_embC[(size_t)t.x * Dd + d0];
    float4 c1 = *(const float4*)&g_embC[(size_t)t.y * Dd + d0];
    float4 c2 = *(const float4*)&g_embC[(size_t)t.z * Dd + d0];
    float4 c3 = *(const float4*)&g_embC[(size_t)t.w * Dd + d0];
    int r = __ldg(&row[e]), q = __ldg(&col[e]);
    float sg = g_sign[e];
    float4 ga = *(const float4*)&g_gsA[(size_t)r * Dd + d0];
    float4 gb = *(const float4*)&g_gsB[(size_t)q * Dd + d0];
    float4 bb = __ldg((const float4*)&eb1[d0]);
    float4 o;
    o.x = fmaxf(ga.x + gb.x + (c0.x + c1.x + c2.x + c3.x) * sg + bb.x, 0.f);
    o.y = fmaxf(ga.y + gb.y + (c0.y + c1.y + c2.y + c3.y) * sg + bb.y, 0.f);
    o.z = fmaxf(ga.z + gb.z + (c0.z + c1.z + c2.z + c3.z) * sg + bb.z, 0.f);
    o.w = fmaxf(ga.w + gb.w + (c0.w + c1.w + c2.w + c3.w) * sg + bb.w, 0.f);
    __stcs((float4*)&g_h[(size_t)e * Dd + d0], o);
}

// ---------------- merged precompute: permuted weights + bcat + bb ---------------
__device__ __forceinline__ int perm32(int p) {
    int j = p & 31;
    int f = ((j >> 1) & 3) * 8 + ((j >> 3) & 3) * 2 + (j & 1);
    return (p & ~31) | f;
}
__global__ void k_prep(const float* __restrict__ ew2, const float* __restrict__ eb2,
                       const float* __restrict__ n1w1, const float* __restrict__ n1b1,
                       const float* __restrict__ n1b2, const float* __restrict__ n2w1,
                       const float* __restrict__ n2w2) {
    int i = blockIdx.x * blockDim.x + threadIdx.x;
    const int base1 = Dd * WCAT_LD;
    const int base2 = base1 + 2 * Dd;
    const int base3 = base2 + Dd;
    const int base4 = base3 + Dd * WP_LD;
    if (i < base1) {
        int k = i / WCAT_LD, p = i - k * WCAT_LD;
        int lp = perm32(p);
        float v = 0.f;
        if (lp < Dd)            v = ew2[(size_t)k * Dd + lp];
        else if (lp < 2 * Dd)   v = g_w2p[(size_t)k * Dd + (lp - Dd)];
        g_wcat[i] = v;
    } else if (i < base2) {
        int j = i - base1;
        if (j < Dd) {
            g_bcat[j] = eb2[j];
        } else {
            int n = j - Dd;
            float s = n1b1[n];
            for (int k = 0; k < Dd; k++) s += eb2[k] * n1w1[(size_t)(Dd + k) * Dd + n];
            g_bcat[j] = s;
        }
    } else if (i < base3) {
        int m = i - base2;
        float s = 0.f;
        for (int k = 0; k < Dd; k++) s += n1b2[k] * n2w1[(size_t)(Dd + k) * Dd + m];
        g_bb[m] = s;
    } else if (i < base4) {
        int j = i - base3;
        int k = j / WP_LD, p = j - k * WP_LD;
        int lp = perm32(p);
        g_w12p[j] = (lp < Dd) ? g_w12[(size_t)k * Dd + lp] : 0.f;
    } else if (i < base4 + Dd * WP_LD) {
        int j = i - base4;
        int k = j / WP_LD, p = j - k * WP_LD;
        int lp = perm32(p);
        g_wn2p[j] = (lp < Dd) ? n2w2[(size_t)k * Dd + lp] : 0.f;
    }
}

// ---------------- graph layer norm ----------------------------------------------
__global__ void k_stats(const int* __restrict__ batch) {
    int n = blockIdx.x;
    float s = 0.f, q = 0.f;
    for (int d = threadIdx.x; d < Dd; d += 128) {
        float v = g_xenc[(size_t)n * Dd + d];
        s += v; q += v * v;
    }
#pragma unroll
    for (int o = 16; o; o >>= 1) {
        s += __shfl_down_sync(0xFFFFFFFFu, s, o);
        q += __shfl_down_sync(0xFFFFFFFFu, q, o);
    }
    __shared__ float ss[4], qq[4];
    int w = threadIdx.x >> 5, l = threadIdx.x & 31;
    if (l == 0) { ss[w] = s; qq[w] = q; }
    __syncthreads();
    if (threadIdx.x == 0) {
        s = ss[0] + ss[1] + ss[2] + ss[3];
        q = qq[0] + qq[1] + qq[2] + qq[3];
        int g = batch[n];
        atomicAdd(&g_gsum[g], s);
        atomicAdd(&g_gsq[g], q);
        atomicAdd(&g_gcnt[g], 1.f);
    }
}
__global__ void k_finalize() {
    int g = threadIdx.x;
    if (g < Gg) {
        float denom = fmaxf(g_gcnt[g] * (float)Dd, 1.f);
        float mean = g_gsum[g] / denom;
        float var = g_gsq[g] / denom - mean * mean;
        g_gmean[g] = mean;
        g_grstd[g] = rsqrtf(var + EPSv);
    }
}
__global__ void k_apply(const int* __restrict__ batch,
                        const float* __restrict__ lnw, const float* __restrict__ lnb,
                        float* __restrict__ out) {
    int i = blockIdx.x * blockDim.x + threadIdx.x;
    if (i >= Nn * 75) return;
    int n = i / 75, d0 = (i - n * 75) * 4;
    int g = __ldg(&batch[n]);
    float mean = g_gmean[g], rstd = g_grstd[g];
    float4 x = *(const float4*)&g_xenc[(size_t)n * Dd + d0];
    float4 wv = __ldg((const float4*)&lnw[d0]);
    float4 bv = __ldg((const float4*)&lnb[d0]);
    float4 o;
    o.x = (x.x - mean) * rstd * wv.x + bv.x;
    o.y = (x.y - mean) * rstd * wv.y + bv.y;
    o.z = (x.z - mean) * rstd * wv.z + bv.z;
    o.w = (x.w - mean) * rstd * wv.w + bv.w;
    *(float4*)&out[(size_t)n * Dd + d0] = o;
}

// ---------------- launch ---------------------------------------------------------
static float* symf(const void* s) {
    void* p = nullptr;
    cudaGetSymbolAddress(&p, s);
    return (float*)p;
}

extern "C" void kernel_launch(void* const* d_in, const int* in_sizes, int n_in,
                              void* d_out, int out_size) {
    const int*   x_tok  = (const int*)d_in[0];
    const int*   ea_tok = (const int*)d_in[1];
    const int*   eidx   = (const int*)d_in[2];
    const int*   ase    = (const int*)d_in[3];
    const int*   batch  = (const int*)d_in[4];
    const float* emb    = (const float*)d_in[5];
    const float* ew1  = (const float*)d_in[6];
    const float* eb1  = (const float*)d_in[7];
    const float* ew2  = (const float*)d_in[8];
    const float* eb2  = (const float*)d_in[9];
    const float* n1w1 = (const float*)d_in[10];
    const float* n1b1 = (const float*)d_in[11];
    const float* n1w2 = (const float*)d_in[12];
    const float* n1b2 = (const float*)d_in[13];
    const float* n2w1 = (const float*)d_in[14];
    const float* n2b1 = (const float*)d_in[15];
    const float* n2w2 = (const float*)d_in[16];
    const float* n2b2 = (const float*)d_in[17];
    const float* lnw  = (const float*)d_in[18];
    const float* lnb  = (const float*)d_in[19];

    const int* row = eidx;
    const int* col = eidx + Ee;

    float* out = (float*)d_out;
    float* edge_out = out + (size_t)Nn * Dd;

    float* pembA = symf(g_embA); float* pembB = symf(g_embB);
    float* pembC = symf(g_embC); float* pembD = symf(g_embD);
    float* pembF = symf(g_embF);
    float* pgsD  = symf(g_gsD);  float* pgsF  = symf(g_gsF);
    float* ph    = symf(g_h);
    float* pagg  = symf(g_agg);  float* pxenc = symf(g_xenc);
    float* pw2p  = symf(g_w2p);  float* pw12  = symf(g_w12);
    float* pwcat = symf(g_wcat); float* pbcat = symf(g_bcat);
    float* pw12p = symf(g_w12p); float* pwn2p = symf(g_wn2p);
    float* pbb   = symf(g_bb);   float* pcnt  = symf(g_cnt);

    const int T256 = 256;

    k_init<<<2048, T256>>>();
    k_signset_cnt<<<(Ee + T256 - 1) / T256, T256>>>(ase, col);

    {
        Bat5 b;
        b.A[0] = emb; b.A[1] = emb; b.A[2] = emb; b.A[3] = emb; b.A[4] = emb;
        b.W[0] = ew1; b.W[1] = ew1 + 300*300; b.W[2] = ew1 + 600*300;
        b.W[3] = n1w1; b.W[4] = n2w1;
        b.O[0] = pembA; b.O[1] = pembB; b.O[2] = pembC; b.O[3] = pembD; b.O[4] = pembF;
        k_gemm_bat<<<dim3(5, (Vv + BMt - 1) / BMt, 5), T256>>>(Vv, Dd, b, Dd);
    }
    {
        Bat5 b;
        b.A[0] = ew2;  b.A[1] = n1w2; b.A[2] = ew2; b.A[3] = ew2; b.A[4] = ew2;
        b.W[0] = n1w1 + 300*300; b.W[1] = n2w1 + 300*300;
        b.W[2] = b.W[0]; b.W[3] = b.W[0]; b.W[4] = b.W[0];
        b.O[0] = pw2p; b.O[1] = pw12; b.O[2] = pw2p; b.O[3] = pw2p; b.O[4] = pw2p;
        k_gemm_bat<<<dim3(5, (Dd + BMt - 1) / BMt, 2), T256>>>(Dd, Dd, b, Dd);
    }
    int prepN = Dd * WCAT_LD + 3 * Dd + 2 * Dd * WP_LD;
    k_prep<<<(prepN + T256 - 1) / T256, T256>>>(ew2, eb2, n1w1, n1b1, n1b2, n2w1, n2w2);

    k_gsum4<<<(Nn * 75 + T256 - 1) / T256, T256>>>(x_tok);
    k_edge_l1<<<(Ee * 75 + T256 - 1) / T256, T256>>>(ea_tok, row, col, eb1);

    // dual GEMM (permuted, ldw=640)
    k_gemm_tc<3><<<dim3(10, Ee / BMt), T256>>>(Ee, WCAT_LD, ph, nullptr, pwcat, WCAT_LD,
                                               pbcat, nullptr, edge_out, pagg,
                                               pgsD, row, col, nullptr);
    // node2 layer-1 (permuted): relu(agg@w12/cnt + n2b1 + gsF + (cnt>0)bb)
    dim3 gN(5, (Nn + BMt - 1) / BMt);
    k_gemm_tc<6><<<gN, T256>>>(Nn, WP_LD, pagg, nullptr, pw12p, WP_LD, n2b1, pbb,
                               ph, nullptr, pgsF, nullptr, nullptr, pcnt);
    // node2 layer-2 (permuted)
    k_gemm_tc<1><<<gN, T256>>>(Nn, WP_LD, ph, nullptr, pwn2p, WP_LD, n2b2, nullptr,
                               pxenc, nullptr, nullptr, nullptr, nullptr, nullptr);

    k_stats<<<Nn, 128>>>(batch);
    k_finalize<<<1, 128>>>();
    k_apply<<<(Nn * 75 + T256 - 1) / T256, T256>>>(batch, lnw, lnb, out);
}

// round 13
// speedup vs baseline: 1.8945x; 1.0167x over previous
#include <cuda_runtime.h>
#include <cstdint>

#define Nn 100000
#define Ee 400000
#define Dd 300
#define Vv 3000
#define Gg 128
#define EPSv 1e-5f
#define WCAT_LD 640
#define WP_LD 320

// ---------------- scratch (device globals) ------------------------------------
__device__ __align__(16) float g_embA[(size_t)Vv * Dd];
__device__ __align__(16) float g_embB[(size_t)Vv * Dd];
__device__ __align__(16) float g_embC[(size_t)Vv * Dd];
__device__ __align__(16) float g_embD[(size_t)Vv * Dd];
__device__ __align__(16) float g_embF[(size_t)Vv * Dd];
__device__ __align__(16) float g_gsA [(size_t)Nn * Dd];
__device__ __align__(16) float g_gsB [(size_t)Nn * Dd];
__device__ __align__(16) float g_gsD [(size_t)Nn * Dd];
__device__ __align__(16) float g_gsF [(size_t)Nn * Dd];
__device__ __align__(16) float g_h   [(size_t)Ee * Dd];
__device__ __align__(16) float g_agg [(size_t)Nn * Dd];
__device__ __align__(16) float g_xenc[(size_t)Nn * Dd];
__device__ __align__(16) float g_w2p [Dd * Dd];           // ew2 @ n1w1_hi
__device__ __align__(16) float g_w12 [Dd * Dd];           // n1w2 @ n2w1_hi
__device__ __align__(16) float g_wcat[Dd * WCAT_LD];      // [300][640] permuted [ew2|w2p|0]
__device__ __align__(16) float g_w12p[Dd * WP_LD];        // w12 permuted [300][320]
__device__ __align__(16) float g_wn2p[Dd * WP_LD];        // n2w2 permuted [300][320]
__device__ __align__(16) float g_bcat[2 * Dd];
__device__ __align__(16) float g_bb[Dd];                  // n1b2 @ n2w1_hi (ct>0 gated)
__device__ float g_cnt[Nn];
__device__ float g_sign[Ee];
__device__ float g_gsum[Gg], g_gsq[Gg], g_gcnt[Gg], g_gmean[Gg], g_grstd[Gg];

// ---------------- merged init (float4 stores) -----------------------------------
__global__ void k_init() {
    long long i = (long long)blockIdx.x * blockDim.x + threadIdx.x;
    long long stride = (long long)gridDim.x * blockDim.x;
    float4 z = make_float4(0.f, 0.f, 0.f, 0.f);
    for (long long j = i; j < (long long)Nn * Dd / 4; j += stride)
        ((float4*)g_agg)[j] = z;
    for (long long j = i; j < Nn / 4; j += stride)
        ((float4*)g_cnt)[j] = z;
    for (long long j = i; j < Ee / 4; j += stride)
        ((float4*)g_sign)[j] = make_float4(1.f, 1.f, 1.f, 1.f);
    if (i < Gg) { g_gsum[i] = 0.f; g_gsq[i] = 0.f; g_gcnt[i] = 0.f; }
}
__global__ void k_signset_cnt(const int* __restrict__ ase, const int* __restrict__ col) {
    int i = blockIdx.x * blockDim.x + threadIdx.x;
    if (i < Ee) atomicAdd(&g_cnt[col[i]], 1.f);
    if (i < Ee / 2) g_sign[ase[i]] = -1.f;
}

// ---------------- mma / cp.async / red helpers ---------------------------------
__device__ __forceinline__ void mma_tf32(float* c, unsigned a0, unsigned a1,
                                         unsigned a2, unsigned a3,
                                         unsigned b0, unsigned b1) {
    asm volatile(
        "mma.sync.aligned.m16n8k8.row.col.f32.tf32.tf32.f32 "
        "{%0,%1,%2,%3}, {%4,%5,%6,%7}, {%8,%9}, {%0,%1,%2,%3};"
        : "+f"(c[0]), "+f"(c[1]), "+f"(c[2]), "+f"(c[3])
        : "r"(a0), "r"(a1), "r"(a2), "r"(a3), "r"(b0), "r"(b1));
}
__device__ __forceinline__ void cpa16(unsigned int dst, const void* src, bool p) {
    int sz = p ? 16 : 0;
    asm volatile("cp.async.cg.shared.global [%0], [%1], 16, %2;"
                 :: "r"(dst), "l"(src), "r"(sz));
}
__device__ __forceinline__ void cpa_commit() {
    asm volatile("cp.async.commit_group;");
}
__device__ __forceinline__ void red_v4(float* p, float4 v) {
    asm volatile("red.global.add.v4.f32 [%0], {%1, %2, %3, %4};"
                 :: "l"(p), "f"(v.x), "f"(v.y), "f"(v.z), "f"(v.w) : "memory");
}

// ---------------- tensor-core GEMM body, K fixed = 300 --------------------------
// Triple-buffered (3 stages, prefetch distance 2, ONE barrier per chunk).
// MODE 0: unpermuted, out0 = v (+bias)                    (precompute path)
// MODE 1: permuted, out0 = v + bias (float4)              (node2-l2)
// MODE 3: permuted dual: gn<300 store; else relu+red.v4   (edge/scatter)
// MODE 6: permuted node2-l1: out0 = relu(v/max(c,1) + bias + add_src + (c>0)bias2)
#define BMt 128
#define BNt 64
#define BKt 16
#define AS_STR 20
#define BS_STR 72
#define NCHUNK 19

template <int MODE>
__device__ __forceinline__ void gemm_body(
    int M, int Nout,
    const float* __restrict__ A, const int* __restrict__ aidx,
    const float* __restrict__ W, int ldw,
    const float* __restrict__ bias, const float* __restrict__ bias2,
    float* __restrict__ out0, float* __restrict__ out1,
    const float* __restrict__ add_src, const int* __restrict__ add_idx,
    const int* __restrict__ scat_idx, const float* __restrict__ cntv)
{
    __shared__ float As[3][BMt * AS_STR];
    __shared__ float Bs[3][BKt * BS_STR];

    const int tid = threadIdx.x;
    const int lane = tid & 31, grp = lane >> 2, tig = lane & 3;
    const int w = tid >> 5;
    const int wm = (w & 3) * 32, wn = (w >> 2) * 32;
    const int tile_n = blockIdx.x * BNt;
    const int tile_m = blockIdx.y * BMt;

    const float* rp[2];
#pragma unroll
    for (int it = 0; it < 2; ++it) {
        int m = (tid >> 2) + it * 64;
        int gm = tile_m + m; if (gm >= M) gm = M - 1;
        int r = aidx ? __ldg(&aidx[gm]) : gm;
        rp[it] = A + (size_t)r * Dd;
    }
    const int ag  = (tid & 3) * 4;
    const int bk  = tid >> 4;
    const int bn4 = (tid & 15) * 4;

    unsigned int sA[3][2], sB[3];
#pragma unroll
    for (int b = 0; b < 3; ++b) {
#pragma unroll
        for (int it = 0; it < 2; ++it) {
            int m = (tid >> 2) + it * 64;
            sA[b][it] = (unsigned int)__cvta_generic_to_shared(&As[b][m * AS_STR + ag]);
        }
        sB[b] = (unsigned int)__cvta_generic_to_shared(&Bs[b][bk * BS_STR + bn4]);
    }

    float acc[2][4][4];
#pragma unroll
    for (int mt = 0; mt < 2; mt++)
#pragma unroll
        for (int nt = 0; nt < 4; nt++)
#pragma unroll
            for (int q = 0; q < 4; q++) acc[mt][nt][q] = 0.f;

    auto load_chunk = [&](int c, int b) {
        int koff = c * BKt;
        int width = 300 - koff; if (width > BKt) width = BKt;
        cpa16(sA[b][0], rp[0] + koff + ag, ag < width);
        cpa16(sA[b][1], rp[1] + koff + ag, ag < width);
        bool pb = (bk < width) && (tile_n + bn4 < Nout);
        cpa16(sB[b], W + (size_t)(koff + bk) * ldw + tile_n + bn4, pb);
    };

    load_chunk(0, 0); cpa_commit();
    load_chunk(1, 1); cpa_commit();

    int st = 0;                 // c % 3
    for (int c = 0; c < NCHUNK; ++c) {
        // pending groups: {c, c+1}; wait until group c complete
        if (c + 1 < NCHUNK) asm volatile("cp.async.wait_group 1;");
        else                asm volatile("cp.async.wait_group 0;");
        __syncthreads();        // all warps done with chunk c-1 -> stage (c+2)%3 free
        if (c + 2 < NCHUNK) {
            int st2 = st + 2; if (st2 >= 3) st2 -= 3;
            load_chunk(c + 2, st2);
            cpa_commit();
        }

        const float* as = As[st];
        const float* bs = Bs[st];
#pragma unroll
        for (int ks = 0; ks < 2; ++ks) {
            const int k0 = ks * 8;
            unsigned af[2][4], bf[4][2];
#pragma unroll
            for (int mt = 0; mt < 2; ++mt) {
                int r0 = (wm + mt * 16 + grp) * AS_STR;
                af[mt][0] = __float_as_uint(as[r0 + k0 + tig]);
                af[mt][1] = __float_as_uint(as[r0 + 8 * AS_STR + k0 + tig]);
                af[mt][2] = __float_as_uint(as[r0 + k0 + tig + 4]);
                af[mt][3] = __float_as_uint(as[r0 + 8 * AS_STR + k0 + tig + 4]);
            }
#pragma unroll
            for (int nt = 0; nt < 4; ++nt) {
                bf[nt][0] = __float_as_uint(bs[(k0 + tig) * BS_STR + wn + nt * 8 + grp]);
                bf[nt][1] = __float_as_uint(bs[(k0 + tig + 4) * BS_STR + wn + nt * 8 + grp]);
            }
#pragma unroll
            for (int mt = 0; mt < 2; ++mt)
#pragma unroll
                for (int nt = 0; nt < 4; ++nt)
                    mma_tf32(acc[mt][nt], af[mt][0], af[mt][1], af[mt][2], af[mt][3],
                             bf[nt][0], bf[nt][1]);
        }
        if (++st == 3) st = 0;
    }

    // ---- epilogue ----
    if (MODE == 1 || MODE == 3 || MODE == 6) {
        const bool hi_half = (MODE == 3) && ((tile_n + wn + 31) >= Dd);
        const int gnb = tile_n + wn + tig * 8;
        const int NL = (MODE == 3) ? 2 * Dd : Dd;
#pragma unroll
        for (int mt = 0; mt < 2; ++mt) {
#pragma unroll
            for (int half = 0; half < 2; ++half) {
                int gm = tile_m + wm + mt * 16 + grp + half * 8;
                if (gm >= M) continue;
                int ai = 0, si = 0;
                float ct = 0.f, inv = 0.f;
                if (MODE == 3) {
                    if (hi_half) { ai = __ldg(&add_idx[gm]); si = __ldg(&scat_idx[gm]); }
                }
                if (MODE == 6) { ct = __ldg(&cntv[gm]); inv = 1.f / fmaxf(ct, 1.f); }
                const int h2 = half * 2;
#pragma unroll
                for (int g = 0; g < 2; ++g) {
                    int gn = gnb + g * 4;
                    if (gn >= NL) continue;
                    float4 v = make_float4(acc[mt][g*2][h2],   acc[mt][g*2][h2+1],
                                           acc[mt][g*2+1][h2], acc[mt][g*2+1][h2+1]);
                    float4 b = __ldg((const float4*)&bias[gn]);
                    if (MODE == 1) {
                        v.x += b.x; v.y += b.y; v.z += b.z; v.w += b.w;
                        *(float4*)&out0[(size_t)gm * Dd + gn] = v;
                    } else if (MODE == 3) {
                        v.x += b.x; v.y += b.y; v.z += b.z; v.w += b.w;
                        if (gn < Dd) {
                            *(float4*)&out0[(size_t)gm * Dd + gn] = v;
                        } else {
                            int gn2 = gn - Dd;
                            float4 a = *(const float4*)&add_src[(size_t)ai * Dd + gn2];
                            v.x = fmaxf(v.x + a.x, 0.f);
                            v.y = fmaxf(v.y + a.y, 0.f);
                            v.z = fmaxf(v.z + a.z, 0.f);
                            v.w = fmaxf(v.w + a.w, 0.f);
                            red_v4(&out1[(size_t)si * Dd + gn2], v);
                        }
                    } else {  // MODE 6: v/max(c,1) + n2b1 + gsF + (c>0)bb
                        float4 a = *(const float4*)&add_src[(size_t)gm * Dd + gn];
                        float4 b2 = make_float4(0.f, 0.f, 0.f, 0.f);
                        if (ct > 0.f) b2 = __ldg((const float4*)&bias2[gn]);
                        v.x = fmaxf(v.x * inv + b.x + b2.x + a.x, 0.f);
                        v.y = fmaxf(v.y * inv + b.y + b2.y + a.y, 0.f);
                        v.z = fmaxf(v.z * inv + b.z + b2.z + a.z, 0.f);
                        v.w = fmaxf(v.w * inv + b.w + b2.w + a.w, 0.f);
                        *(float4*)&out0[(size_t)gm * Dd + gn] = v;
                    }
                }
            }
        }
    } else {  // MODE 0
#pragma unroll
        for (int mt = 0; mt < 2; ++mt) {
#pragma unroll
            for (int half = 0; half < 2; ++half) {
                int gm = tile_m + wm + mt * 16 + grp + half * 8;
                if (gm >= M) continue;
#pragma unroll
                for (int nt = 0; nt < 4; ++nt) {
                    int gn = tile_n + wn + nt * 8 + tig * 2;
                    if (gn >= Nout) continue;
                    float2 v = make_float2(acc[mt][nt][half * 2], acc[mt][nt][half * 2 + 1]);
                    if (bias) {
                        float2 b = __ldg((const float2*)&bias[gn]);
                        v.x += b.x; v.y += b.y;
                    }
                    *(float2*)&out0[(size_t)gm * Dd + gn] = v;
                }
            }
        }
    }
}

template <int MODE>
__global__ __launch_bounds__(256) void k_gemm_tc(
    int M, int Nout,
    const float* __restrict__ A, const int* __restrict__ aidx,
    const float* __restrict__ W, int ldw,
    const float* __restrict__ bias, const float* __restrict__ bias2,
    float* __restrict__ out0, float* __restrict__ out1,
    const float* __restrict__ add_src, const int* __restrict__ add_idx,
    const int* __restrict__ scat_idx, const float* __restrict__ cntv)
{
    gemm_body<MODE>(M, Nout, A, aidx, W, ldw, bias, bias2, out0, out1,
                    add_src, add_idx, scat_idx, cntv);
}

struct Bat5 { const float* A[5]; const float* W[5]; float* O[5]; };

__global__ __launch_bounds__(256) void k_gemm_bat(int M, int Nout, Bat5 bat, int ldw) {
    int z = blockIdx.z;
    gemm_body<0>(M, Nout, bat.A[z], nullptr, bat.W[z], ldw, nullptr, nullptr,
                 bat.O[z], nullptr, nullptr, nullptr, nullptr, nullptr);
}

// ---------------- gather-sum of 4 pre-transformed tables (float4/thread) -------
__global__ void k_gsum4(const int* __restrict__ tok) {
    int i = blockIdx.x * blockDim.x + threadIdx.x;
    if (i >= Nn * 75) return;
    int n = i / 75, d0 = (i - n * 75) * 4;
    int4 t = ((const int4*)tok)[n];
    size_t o0 = (size_t)t.x * Dd + d0, o1 = (size_t)t.y * Dd + d0;
    size_t o2 = (size_t)t.z * Dd + d0, o3 = (size_t)t.w * Dd + d0;
    size_t di = (size_t)n * Dd + d0;
    float4 r, a0, a1, a2, a3;
    a0 = *(const float4*)&g_embA[o0]; a1 = *(const float4*)&g_embA[o1];
    a2 = *(const float4*)&g_embA[o2]; a3 = *(const float4*)&g_embA[o3];
    r.x = a0.x + a1.x + a2.x + a3.x; r.y = a0.y + a1.y + a2.y + a3.y;
    r.z = a0.z + a1.z + a2.z + a3.z; r.w = a0.w + a1.w + a2.w + a3.w;
    *(float4*)&g_gsA[di] = r;
    a0 = *(const float4*)&g_embB[o0]; a1 = *(const float4*)&g_embB[o1];
    a2 = *(const float4*)&g_embB[o2]; a3 = *(const float4*)&g_embB[o3];
    r.x = a0.x + a1.x + a2.x + a3.x; r.y = a0.y + a1.y + a2.y + a3.y;
    r.z = a0.z + a1.z + a2.z + a3.z; r.w = a0.w + a1.w + a2.w + a3.w;
    *(float4*)&g_gsB[di] = r;
    a0 = *(const float4*)&g_embD[o0]; a1 = *(const float4*)&g_embD[o1];
    a2 = *(const float4*)&g_embD[o2]; a3 = *(const float4*)&g_embD[o3];
    r.x = a0.x + a1.x + a2.x + a3.x; r.y = a0.y + a1.y + a2.y + a3.y;
    r.z = a0.z + a1.z + a2.z + a3.z; r.w = a0.w + a1.w + a2.w + a3.w;
    *(float4*)&g_gsD[di] = r;
    a0 = *(const float4*)&g_embF[o0]; a1 = *(const float4*)&g_embF[o1];
    a2 = *(const float4*)&g_embF[o2]; a3 = *(const float4*)&g_embF[o3];
    r.x = a0.x + a1.x + a2.x + a3.x; r.y = a0.y + a1.y + a2.y + a3.y;
    r.z = a0.z + a1.z + a2.z + a3.z; r.w = a0.w + a1.w + a2.w + a3.w;
    *(float4*)&g_gsF[di] = r;
}

// ---------------- edge layer-1 elementwise ---------------------------------------
__global__ void k_edge_l1(const int* __restrict__ ea_tok,
                          const int* __restrict__ row, const int* __restrict__ col,
                          const float* __restrict__ eb1) {
    int i = blockIdx.x * blockDim.x + threadIdx.x;
    if (i >= Ee * 75) return;
    int e = i / 75, d0 = (i - e * 75) * 4;
    int4 t = ((const int4*)ea_tok)[e];
    float4 c0 = *(const float4*)&g_embC[(size_t)t.x * Dd + d0];
    float4 c1 = *(const float4*)&g_embC[(size_t)t.y * Dd + d0];
    float4 c2 = *(const float4*)&g_embC[(size_t)t.z * Dd + d0];
    float4 c3 = *(const float4*)&g_embC[(size_t)t.w * Dd + d0];
    int r = __ldg(&row[e]), q = __ldg(&col[e]);
    float sg = g_sign[e];
    float4 ga = *(const float4*)&g_gsA[(size_t)r * Dd + d0];
    float4 gb = *(const float4*)&g_gsB[(size_t)q * Dd + d0];
    float4 bb = __ldg((const float4*)&eb1[d0]);
    float4 o;
    o.x = fmaxf(ga.x + gb.x + (c0.x + c1.x + c2.x + c3.x) * sg + bb.x, 0.f);
    o.y = fmaxf(ga.y + gb.y + (c0.y + c1.y + c2.y + c3.y) * sg + bb.y, 0.f);
    o.z = fmaxf(ga.z + gb.z + (c0.z + c1.z + c2.z + c3.z) * sg + bb.z, 0.f);
    o.w = fmaxf(ga.w + gb.w + (c0.w + c1.w + c2.w + c3.w) * sg + bb.w, 0.f);
    __stcs((float4*)&g_h[(size_t)e * Dd + d0], o);
}

// ---------------- merged precompute: permuted weights + bcat + bb ---------------
__device__ __forceinline__ int perm32(int p) {
    int j = p & 31;
    int f = ((j >> 1) & 3) * 8 + ((j >> 3) & 3) * 2 + (j & 1);
    return (p & ~31) | f;
}
__global__ void k_prep(const float* __restrict__ ew2, const float* __restrict__ eb2,
                       const float* __restrict__ n1w1, const float* __restrict__ n1b1,
                       const float* __restrict__ n1b2, const float* __restrict__ n2w1,
                       const float* __restrict__ n2w2) {
    int i = blockIdx.x * blockDim.x + threadIdx.x;
    const int base1 = Dd * WCAT_LD;
    const int base2 = base1 + 2 * Dd;
    const int base3 = base2 + Dd;
    const int base4 = base3 + Dd * WP_LD;
    if (i < base1) {
        int k = i / WCAT_LD, p = i - k * WCAT_LD;
        int lp = perm32(p);
        float v = 0.f;
        if (lp < Dd)            v = ew2[(size_t)k * Dd + lp];
        else if (lp < 2 * Dd)   v = g_w2p[(size_t)k * Dd + (lp - Dd)];
        g_wcat[i] = v;
    } else if (i < base2) {
        int j = i - base1;
        if (j < Dd) {
            g_bcat[j] = eb2[j];
        } else {
            int n = j - Dd;
            float s = n1b1[n];
            for (int k = 0; k < Dd; k++) s += eb2[k] * n1w1[(size_t)(Dd + k) * Dd + n];
            g_bcat[j] = s;
        }
    } else if (i < base3) {
        int m = i - base2;
        float s = 0.f;
        for (int k = 0; k < Dd; k++) s += n1b2[k] * n2w1[(size_t)(Dd + k) * Dd + m];
        g_bb[m] = s;
    } else if (i < base4) {
        int j = i - base3;
        int k = j / WP_LD, p = j - k * WP_LD;
        int lp = perm32(p);
        g_w12p[j] = (lp < Dd) ? g_w12[(size_t)k * Dd + lp] : 0.f;
    } else if (i < base4 + Dd * WP_LD) {
        int j = i - base4;
        int k = j / WP_LD, p = j - k * WP_LD;
        int lp = perm32(p);
        g_wn2p[j] = (lp < Dd) ? n2w2[(size_t)k * Dd + lp] : 0.f;
    }
}

// ---------------- graph layer norm ----------------------------------------------
__global__ void k_stats(const int* __restrict__ batch) {
    int n = blockIdx.x;
    float s = 0.f, q = 0.f;
    for (int d = threadIdx.x; d < Dd; d += 128) {
        float v = g_xenc[(size_t)n * Dd + d];
        s += v; q += v * v;
    }
#pragma unroll
    for (int o = 16; o; o >>= 1) {
        s += __shfl_down_sync(0xFFFFFFFFu, s, o);
        q += __shfl_down_sync(0xFFFFFFFFu, q, o);
    }
    __shared__ float ss[4], qq[4];
    int w = threadIdx.x >> 5, l = threadIdx.x & 31;
    if (l == 0) { ss[w] = s; qq[w] = q; }
    __syncthreads();
    if (threadIdx.x == 0) {
        s = ss[0] + ss[1] + ss[2] + ss[3];
        q = qq[0] + qq[1] + qq[2] + qq[3];
        int g = batch[n];
        atomicAdd(&g_gsum[g], s);
        atomicAdd(&g_gsq[g], q);
        atomicAdd(&g_gcnt[g], 1.f);
    }
}
__global__ void k_finalize() {
    int g = threadIdx.x;
    if (g < Gg) {
        float denom = fmaxf(g_gcnt[g] * (float)Dd, 1.f);
        float mean = g_gsum[g] / denom;
        float var = g_gsq[g] / denom - mean * mean;
        g_gmean[g] = mean;
        g_grstd[g] = rsqrtf(var + EPSv);
    }
}
__global__ void k_apply(const int* __restrict__ batch,
                        const float* __restrict__ lnw, const float* __restrict__ lnb,
                        float* __restrict__ out) {
    int i = blockIdx.x * blockDim.x + threadIdx.x;
    if (i >= Nn * 75) return;
    int n = i / 75, d0 = (i - n * 75) * 4;
    int g = __ldg(&batch[n]);
    float mean = g_gmean[g], rstd = g_grstd[g];
    float4 x = *(const float4*)&g_xenc[(size_t)n * Dd + d0];
    float4 wv = __ldg((const float4*)&lnw[d0]);
    float4 bv = __ldg((const float4*)&lnb[d0]);
    float4 o;
    o.x = (x.x - mean) * rstd * wv.x + bv.x;
    o.y = (x.y - mean) * rstd * wv.y + bv.y;
    o.z = (x.z - mean) * rstd * wv.z + bv.z;
    o.w = (x.w - mean) * rstd * wv.w + bv.w;
    *(float4*)&out[(size_t)n * Dd + d0] = o;
}

// ---------------- launch ---------------------------------------------------------
static float* symf(const void* s) {
    void* p = nullptr;
    cudaGetSymbolAddress(&p, s);
    return (float*)p;
}

extern "C" void kernel_launch(void* const* d_in, const int* in_sizes, int n_in,
                              void* d_out, int out_size) {
    const int*   x_tok  = (const int*)d_in[0];
    const int*   ea_tok = (const int*)d_in[1];
    const int*   eidx   = (const int*)d_in[2];
    const int*   ase    = (const int*)d_in[3];
    const int*   batch  = (const int*)d_in[4];
    const float* emb    = (const float*)d_in[5];
    const float* ew1  = (const float*)d_in[6];
    const float* eb1  = (const float*)d_in[7];
    const float* ew2  = (const float*)d_in[8];
    const float* eb2  = (const float*)d_in[9];
    const float* n1w1 = (const float*)d_in[10];
    const float* n1b1 = (const float*)d_in[11];
    const float* n1w2 = (const float*)d_in[12];
    const float* n1b2 = (const float*)d_in[13];
    const float* n2w1 = (const float*)d_in[14];
    const float* n2b1 = (const float*)d_in[15];
    const float* n2w2 = (const float*)d_in[16];
    const float* n2b2 = (const float*)d_in[17];
    const float* lnw  = (const float*)d_in[18];
    const float* lnb  = (const float*)d_in[19];

    const int* row = eidx;
    const int* col = eidx + Ee;

    float* out = (float*)d_out;
    float* edge_out = out + (size_t)Nn * Dd;

    float* pembA = symf(g_embA); float* pembB = symf(g_embB);
    float* pembC = symf(g_embC); float* pembD = symf(g_embD);
    float* pembF = symf(g_embF);
    float* pgsD  = symf(g_gsD);  float* pgsF  = symf(g_gsF);
    float* ph    = symf(g_h);
    float* pagg  = symf(g_agg);  float* pxenc = symf(g_xenc);
    float* pw2p  = symf(g_w2p);  float* pw12  = symf(g_w12);
    float* pwcat = symf(g_wcat); float* pbcat = symf(g_bcat);
    float* pw12p = symf(g_w12p); float* pwn2p = symf(g_wn2p);
    float* pbb   = symf(g_bb);   float* pcnt  = symf(g_cnt);

    const int T256 = 256;

    k_init<<<2048, T256>>>();
    k_signset_cnt<<<(Ee + T256 - 1) / T256, T256>>>(ase, col);

    {
        Bat5 b;
        b.A[0] = emb; b.A[1] = emb; b.A[2] = emb; b.A[3] = emb; b.A[4] = emb;
        b.W[0] = ew1; b.W[1] = ew1 + 300*300; b.W[2] = ew1 + 600*300;
        b.W[3] = n1w1; b.W[4] = n2w1;
        b.O[0] = pembA; b.O[1] = pembB; b.O[2] = pembC; b.O[3] = pembD; b.O[4] = pembF;
        k_gemm_bat<<<dim3(5, (Vv + BMt - 1) / BMt, 5), T256>>>(Vv, Dd, b, Dd);
    }
    {
        Bat5 b;
        b.A[0] = ew2;  b.A[1] = n1w2; b.A[2] = ew2; b.A[3] = ew2; b.A[4] = ew2;
        b.W[0] = n1w1 + 300*300; b.W[1] = n2w1 + 300*300;
        b.W[2] = b.W[0]; b.W[3] = b.W[0]; b.W[4] = b.W[0];
        b.O[0] = pw2p; b.O[1] = pw12; b.O[2] = pw2p; b.O[3] = pw2p; b.O[4] = pw2p;
        k_gemm_bat<<<dim3(5, (Dd + BMt - 1) / BMt, 2), T256>>>(Dd, Dd, b, Dd);
    }
    int prepN = Dd * WCAT_LD + 3 * Dd + 2 * Dd * WP_LD;
    k_prep<<<(prepN + T256 - 1) / T256, T256>>>(ew2, eb2, n1w1, n1b1, n1b2, n2w1, n2w2);

    k_gsum4<<<(Nn * 75 + T256 - 1) / T256, T256>>>(x_tok);
    k_edge_l1<<<(Ee * 75 + T256 - 1) / T256, T256>>>(ea_tok, row, col, eb1);

    // dual GEMM (permuted, ldw=640)
    k_gemm_tc<3><<<dim3(10, Ee / BMt), T256>>>(Ee, WCAT_LD, ph, nullptr, pwcat, WCAT_LD,
                                               pbcat, nullptr, edge_out, pagg,
                                               pgsD, row, col, nullptr);
    // node2 layer-1 (permuted): relu(agg@w12/cnt + n2b1 + gsF + (cnt>0)bb)
    dim3 gN(5, (Nn + BMt - 1) / BMt);
    k_gemm_tc<6><<<gN, T256>>>(Nn, WP_LD, pagg, nullptr, pw12p, WP_LD, n2b1, pbb,
                               ph, nullptr, pgsF, nullptr, nullptr, pcnt);
    // node2 layer-2 (permuted)
    k_gemm_tc<1><<<gN, T256>>>(Nn, WP_LD, ph, nullptr, pwn2p, WP_LD, n2b2, nullptr,
                               pxenc, nullptr, nullptr, nullptr, nullptr, nullptr);

    k_stats<<<Nn, 128>>>(batch);
    k_finalize<<<1, 128>>>();
    k_apply<<<(Nn * 75 + T256 - 1) / T256, T256>>>(batch, lnw, lnb, out);
}

// round 14
// speedup vs baseline: 1.9282x; 1.0177x over previous
#include <cuda_runtime.h>
#include <cstdint>

#define Nn 100000
#define Ee 400000
#define Dd 300
#define Vv 3000
#define Gg 128
#define EPSv 1e-5f
#define WCAT_LD 640
#define WP_LD 320

// ---------------- scratch (device globals) ------------------------------------
__device__ __align__(16) float g_embA[(size_t)Vv * Dd];
__device__ __align__(16) float g_embB[(size_t)Vv * Dd];
__device__ __align__(16) float g_embC[(size_t)Vv * Dd];
__device__ __align__(16) float g_embD[(size_t)Vv * Dd];
__device__ __align__(16) float g_embF[(size_t)Vv * Dd];
__device__ __align__(16) float g_gsA [(size_t)Nn * Dd];
__device__ __align__(16) float g_gsB [(size_t)Nn * Dd];
__device__ __align__(16) float g_gsD [(size_t)Nn * Dd];
__device__ __align__(16) float g_gsF [(size_t)Nn * Dd];
__device__ __align__(16) float g_h   [(size_t)Ee * Dd];
__device__ __align__(16) float g_agg [(size_t)Nn * Dd];
__device__ __align__(16) float g_xenc[(size_t)Nn * Dd];
__device__ __align__(16) float g_w2p [Dd * Dd];           // ew2 @ n1w1_hi
__device__ __align__(16) float g_w12 [Dd * Dd];           // n1w2 @ n2w1_hi
__device__ __align__(16) float g_wcat[Dd * WCAT_LD];      // [300][640] permuted [ew2|w2p|0]
__device__ __align__(16) float g_w12p[Dd * WP_LD];        // w12 permuted [300][320]
__device__ __align__(16) float g_wn2p[Dd * WP_LD];        // n2w2 permuted [300][320]
__device__ __align__(16) float g_bcat[2 * Dd];
__device__ __align__(16) float g_bb[Dd];                  // n1b2 @ n2w1_hi (ct>0 gated)
__device__ float g_cnt[Nn];
__device__ float g_sign[Ee];
__device__ float g_gsum[Gg], g_gsq[Gg], g_gcnt[Gg], g_gmean[Gg], g_grstd[Gg];

// ---------------- merged init (float4 stores) -----------------------------------
__global__ void k_init() {
    long long i = (long long)blockIdx.x * blockDim.x + threadIdx.x;
    long long stride = (long long)gridDim.x * blockDim.x;
    float4 z = make_float4(0.f, 0.f, 0.f, 0.f);
    for (long long j = i; j < (long long)Nn * Dd / 4; j += stride)
        ((float4*)g_agg)[j] = z;
    for (long long j = i; j < Nn / 4; j += stride)
        ((float4*)g_cnt)[j] = z;
    for (long long j = i; j < Ee / 4; j += stride)
        ((float4*)g_sign)[j] = make_float4(1.f, 1.f, 1.f, 1.f);
    if (i < Gg) { g_gsum[i] = 0.f; g_gsq[i] = 0.f; g_gcnt[i] = 0.f; }
}

// ---------------- mma / cp.async / red helpers ---------------------------------
__device__ __forceinline__ void mma_tf32(float* c, unsigned a0, unsigned a1,
                                         unsigned a2, unsigned a3,
                                         unsigned b0, unsigned b1) {
    asm volatile(
        "mma.sync.aligned.m16n8k8.row.col.f32.tf32.tf32.f32 "
        "{%0,%1,%2,%3}, {%4,%5,%6,%7}, {%8,%9}, {%0,%1,%2,%3};"
        : "+f"(c[0]), "+f"(c[1]), "+f"(c[2]), "+f"(c[3])
        : "r"(a0), "r"(a1), "r"(a2), "r"(a3), "r"(b0), "r"(b1));
}
__device__ __forceinline__ void cpa16(unsigned int dst, const void* src, bool p) {
    int sz = p ? 16 : 0;
    asm volatile("cp.async.cg.shared.global [%0], [%1], 16, %2;"
                 :: "r"(dst), "l"(src), "r"(sz));
}
__device__ __forceinline__ void cpa_commit() {
    asm volatile("cp.async.commit_group;");
}
__device__ __forceinline__ void red_v4(float* p, float4 v) {
    asm volatile("red.global.add.v4.f32 [%0], {%1, %2, %3, %4};"
                 :: "l"(p), "f"(v.x), "f"(v.y), "f"(v.z), "f"(v.w) : "memory");
}

// ---------------- tensor-core GEMM body, K fixed = 300 --------------------------
// Triple-buffered (3 stages, prefetch distance 2, ONE barrier per chunk).
// MODE 0: unpermuted, out0 = v (+bias)                    (precompute path)
// MODE 1: permuted, out0 = v + bias (float4)              (node2-l2)
// MODE 3: permuted dual: gn<300 stcs store; else relu+red.v4
// MODE 6: permuted node2-l1: out0 = relu(v/max(c,1) + bias + add_src + (c>0)bias2)
#define BMt 128
#define BNt 64
#define BKt 16
#define AS_STR 20
#define BS_STR 72
#define NCHUNK 19

template <int MODE>
__device__ __forceinline__ void gemm_body(
    int M, int Nout,
    const float* __restrict__ A, const int* __restrict__ aidx,
    const float* __restrict__ W, int ldw,
    const float* __restrict__ bias, const float* __restrict__ bias2,
    float* __restrict__ out0, float* __restrict__ out1,
    const float* __restrict__ add_src, const int* __restrict__ add_idx,
    const int* __restrict__ scat_idx, const float* __restrict__ cntv)
{
    __shared__ float As[3][BMt * AS_STR];
    __shared__ float Bs[3][BKt * BS_STR];

    const int tid = threadIdx.x;
    const int lane = tid & 31, grp = lane >> 2, tig = lane & 3;
    const int w = tid >> 5;
    const int wm = (w & 3) * 32, wn = (w >> 2) * 32;
    const int tile_n = blockIdx.x * BNt;
    const int tile_m = blockIdx.y * BMt;

    const float* rp[2];
#pragma unroll
    for (int it = 0; it < 2; ++it) {
        int m = (tid >> 2) + it * 64;
        int gm = tile_m + m; if (gm >= M) gm = M - 1;
        int r = aidx ? __ldg(&aidx[gm]) : gm;
        rp[it] = A + (size_t)r * Dd;
    }
    const int ag  = (tid & 3) * 4;
    const int bk  = tid >> 4;
    const int bn4 = (tid & 15) * 4;

    unsigned int sA[3][2], sB[3];
#pragma unroll
    for (int b = 0; b < 3; ++b) {
#pragma unroll
        for (int it = 0; it < 2; ++it) {
            int m = (tid >> 2) + it * 64;
            sA[b][it] = (unsigned int)__cvta_generic_to_shared(&As[b][m * AS_STR + ag]);
        }
        sB[b] = (unsigned int)__cvta_generic_to_shared(&Bs[b][bk * BS_STR + bn4]);
    }

    float acc[2][4][4];
#pragma unroll
    for (int mt = 0; mt < 2; mt++)
#pragma unroll
        for (int nt = 0; nt < 4; nt++)
#pragma unroll
            for (int q = 0; q < 4; q++) acc[mt][nt][q] = 0.f;

    auto load_chunk = [&](int c, int b) {
        int koff = c * BKt;
        int width = 300 - koff; if (width > BKt) width = BKt;
        cpa16(sA[b][0], rp[0] + koff + ag, ag < width);
        cpa16(sA[b][1], rp[1] + koff + ag, ag < width);
        bool pb = (bk < width) && (tile_n + bn4 < Nout);
        cpa16(sB[b], W + (size_t)(koff + bk) * ldw + tile_n + bn4, pb);
    };

    load_chunk(0, 0); cpa_commit();
    load_chunk(1, 1); cpa_commit();

    int st = 0;
    for (int c = 0; c < NCHUNK; ++c) {
        if (c + 1 < NCHUNK) asm volatile("cp.async.wait_group 1;");
        else                asm volatile("cp.async.wait_group 0;");
        __syncthreads();
        if (c + 2 < NCHUNK) {
            int st2 = st + 2; if (st2 >= 3) st2 -= 3;
            load_chunk(c + 2, st2);
            cpa_commit();
        }

        const float* as = As[st];
        const float* bs = Bs[st];
#pragma unroll
        for (int ks = 0; ks < 2; ++ks) {
            const int k0 = ks * 8;
            unsigned af[2][4], bf[4][2];
#pragma unroll
            for (int mt = 0; mt < 2; ++mt) {
                int r0 = (wm + mt * 16 + grp) * AS_STR;
                af[mt][0] = __float_as_uint(as[r0 + k0 + tig]);
                af[mt][1] = __float_as_uint(as[r0 + 8 * AS_STR + k0 + tig]);
                af[mt][2] = __float_as_uint(as[r0 + k0 + tig + 4]);
                af[mt][3] = __float_as_uint(as[r0 + 8 * AS_STR + k0 + tig + 4]);
            }
#pragma unroll
            for (int nt = 0; nt < 4; ++nt) {
                bf[nt][0] = __float_as_uint(bs[(k0 + tig) * BS_STR + wn + nt * 8 + grp]);
                bf[nt][1] = __float_as_uint(bs[(k0 + tig + 4) * BS_STR + wn + nt * 8 + grp]);
            }
#pragma unroll
            for (int mt = 0; mt < 2; ++mt)
#pragma unroll
                for (int nt = 0; nt < 4; ++nt)
                    mma_tf32(acc[mt][nt], af[mt][0], af[mt][1], af[mt][2], af[mt][3],
                             bf[nt][0], bf[nt][1]);
        }
        if (++st == 3) st = 0;
    }

    // ---- epilogue ----
    if (MODE == 1 || MODE == 3 || MODE == 6) {
        const bool hi_half = (MODE == 3) && ((tile_n + wn + 31) >= Dd);
        const int gnb = tile_n + wn + tig * 8;
        const int NL = (MODE == 3) ? 2 * Dd : Dd;
#pragma unroll
        for (int mt = 0; mt < 2; ++mt) {
#pragma unroll
            for (int half = 0; half < 2; ++half) {
                int gm = tile_m + wm + mt * 16 + grp + half * 8;
                if (gm >= M) continue;
                int ai = 0, si = 0;
                float ct = 0.f, inv = 0.f;
                if (MODE == 3) {
                    if (hi_half) { ai = __ldg(&add_idx[gm]); si = __ldg(&scat_idx[gm]); }
                }
                if (MODE == 6) { ct = __ldg(&cntv[gm]); inv = 1.f / fmaxf(ct, 1.f); }
                const int h2 = half * 2;
#pragma unroll
                for (int g = 0; g < 2; ++g) {
                    int gn = gnb + g * 4;
                    if (gn >= NL) continue;
                    float4 v = make_float4(acc[mt][g*2][h2],   acc[mt][g*2][h2+1],
                                           acc[mt][g*2+1][h2], acc[mt][g*2+1][h2+1]);
                    float4 b = __ldg((const float4*)&bias[gn]);
                    if (MODE == 1) {
                        v.x += b.x; v.y += b.y; v.z += b.z; v.w += b.w;
                        *(float4*)&out0[(size_t)gm * Dd + gn] = v;
                    } else if (MODE == 3) {
                        v.x += b.x; v.y += b.y; v.z += b.z; v.w += b.w;
                        if (gn < Dd) {
                            // streaming store: edge_out is final output, never re-read;
                            // keep L2 for gsD gathers + agg atomics
                            __stcs((float4*)&out0[(size_t)gm * Dd + gn], v);
                        } else {
                            int gn2 = gn - Dd;
                            float4 a = *(const float4*)&add_src[(size_t)ai * Dd + gn2];
                            v.x = fmaxf(v.x + a.x, 0.f);
                            v.y = fmaxf(v.y + a.y, 0.f);
                            v.z = fmaxf(v.z + a.z, 0.f);
                            v.w = fmaxf(v.w + a.w, 0.f);
                            red_v4(&out1[(size_t)si * Dd + gn2], v);
                        }
                    } else {  // MODE 6: v/max(c,1) + n2b1 + gsF + (c>0)bb
                        float4 a = *(const float4*)&add_src[(size_t)gm * Dd + gn];
                        float4 b2 = make_float4(0.f, 0.f, 0.f, 0.f);
                        if (ct > 0.f) b2 = __ldg((const float4*)&bias2[gn]);
                        v.x = fmaxf(v.x * inv + b.x + b2.x + a.x, 0.f);
                        v.y = fmaxf(v.y * inv + b.y + b2.y + a.y, 0.f);
                        v.z = fmaxf(v.z * inv + b.z + b2.z + a.z, 0.f);
                        v.w = fmaxf(v.w * inv + b.w + b2.w + a.w, 0.f);
                        *(float4*)&out0[(size_t)gm * Dd + gn] = v;
                    }
                }
            }
        }
    } else {  // MODE 0
#pragma unroll
        for (int mt = 0; mt < 2; ++mt) {
#pragma unroll
            for (int half = 0; half < 2; ++half) {
                int gm = tile_m + wm + mt * 16 + grp + half * 8;
                if (gm >= M) continue;
#pragma unroll
                for (int nt = 0; nt < 4; ++nt) {
                    int gn = tile_n + wn + nt * 8 + tig * 2;
                    if (gn >= Nout) continue;
                    float2 v = make_float2(acc[mt][nt][half * 2], acc[mt][nt][half * 2 + 1]);
                    if (bias) {
                        float2 b = __ldg((const float2*)&bias[gn]);
                        v.x += b.x; v.y += b.y;
                    }
                    *(float2*)&out0[(size_t)gm * Dd + gn] = v;
                }
            }
        }
    }
}

template <int MODE>
__global__ __launch_bounds__(256) void k_gemm_tc(
    int M, int Nout,
    const float* __restrict__ A, const int* __restrict__ aidx,
    const float* __restrict__ W, int ldw,
    const float* __restrict__ bias, const float* __restrict__ bias2,
    float* __restrict__ out0, float* __restrict__ out1,
    const float* __restrict__ add_src, const int* __restrict__ add_idx,
    const int* __restrict__ scat_idx, const float* __restrict__ cntv)
{
    gemm_body<MODE>(M, Nout, A, aidx, W, ldw, bias, bias2, out0, out1,
                    add_src, add_idx, scat_idx, cntv);
}

struct Bat5 { const float* A[5]; const float* W[5]; float* O[5]; };

__global__ __launch_bounds__(256) void k_gemm_bat(int M, int Nout, Bat5 bat, int ldw) {
    int z = blockIdx.z;
    gemm_body<0>(M, Nout, bat.A[z], nullptr, bat.W[z], ldw, nullptr, nullptr,
                 bat.O[z], nullptr, nullptr, nullptr, nullptr, nullptr);
}

// ---------------- gather-sums + folded sign/cnt (first Ee threads) --------------
__global__ void k_gsum4(const int* __restrict__ tok,
                        const int* __restrict__ ase, const int* __restrict__ col) {
    int i = blockIdx.x * blockDim.x + threadIdx.x;
    if (i < Ee) atomicAdd(&g_cnt[__ldg(&col[i])], 1.f);
    if (i < Ee / 2) g_sign[__ldg(&ase[i])] = -1.f;
    if (i >= Nn * 75) return;
    int n = i / 75, d0 = (i - n * 75) * 4;
    int4 t = ((const int4*)tok)[n];
    size_t o0 = (size_t)t.x * Dd + d0, o1 = (size_t)t.y * Dd + d0;
    size_t o2 = (size_t)t.z * Dd + d0, o3 = (size_t)t.w * Dd + d0;
    size_t di = (size_t)n * Dd + d0;
    float4 r, a0, a1, a2, a3;
    a0 = *(const float4*)&g_embA[o0]; a1 = *(const float4*)&g_embA[o1];
    a2 = *(const float4*)&g_embA[o2]; a3 = *(const float4*)&g_embA[o3];
    r.x = a0.x + a1.x + a2.x + a3.x; r.y = a0.y + a1.y + a2.y + a3.y;
    r.z = a0.z + a1.z + a2.z + a3.z; r.w = a0.w + a1.w + a2.w + a3.w;
    *(float4*)&g_gsA[di] = r;
    a0 = *(const float4*)&g_embB[o0]; a1 = *(const float4*)&g_embB[o1];
    a2 = *(const float4*)&g_embB[o2]; a3 = *(const float4*)&g_embB[o3];
    r.x = a0.x + a1.x + a2.x + a3.x; r.y = a0.y + a1.y + a2.y + a3.y;
    r.z = a0.z + a1.z + a2.z + a3.z; r.w = a0.w + a1.w + a2.w + a3.w;
    *(float4*)&g_gsB[di] = r;
    a0 = *(const float4*)&g_embD[o0]; a1 = *(const float4*)&g_embD[o1];
    a2 = *(const float4*)&g_embD[o2]; a3 = *(const float4*)&g_embD[o3];
    r.x = a0.x + a1.x + a2.x + a3.x; r.y = a0.y + a1.y + a2.y + a3.y;
    r.z = a0.z + a1.z + a2.z + a3.z; r.w = a0.w + a1.w + a2.w + a3.w;
    *(float4*)&g_gsD[di] = r;
    a0 = *(const float4*)&g_embF[o0]; a1 = *(const float4*)&g_embF[o1];
    a2 = *(const float4*)&g_embF[o2]; a3 = *(const float4*)&g_embF[o3];
    r.x = a0.x + a1.x + a2.x + a3.x; r.y = a0.y + a1.y + a2.y + a3.y;
    r.z = a0.z + a1.z + a2.z + a3.z; r.w = a0.w + a1.w + a2.w + a3.w;
    *(float4*)&g_gsF[di] = r;
}

// ---------------- edge layer-1 elementwise ---------------------------------------
__global__ void k_edge_l1(const int* __restrict__ ea_tok,
                          const int* __restrict__ row, const int* __restrict__ col,
                          const float* __restrict__ eb1) {
    int i = blockIdx.x * blockDim.x + threadIdx.x;
    if (i >= Ee * 75) return;
    int e = i / 75, d0 = (i - e * 75) * 4;
    int4 t = ((const int4*)ea_tok)[e];
    float4 c0 = *(const float4*)&g_embC[(size_t)t.x * Dd + d0];
    float4 c1 = *(const float4*)&g_embC[(size_t)t.y * Dd + d0];
    float4 c2 = *(const float4*)&g_embC[(size_t)t.z * Dd + d0];
    float4 c3 = *(const float4*)&g_embC[(size_t)t.w * Dd + d0];
    int r = __ldg(&row[e]), q = __ldg(&col[e]);
    float sg = g_sign[e];
    float4 ga = *(const float4*)&g_gsA[(size_t)r * Dd + d0];
    float4 gb = *(const float4*)&g_gsB[(size_t)q * Dd + d0];
    float4 bb = __ldg((const float4*)&eb1[d0]);
    float4 o;
    o.x = fmaxf(ga.x + gb.x + (c0.x + c1.x + c2.x + c3.x) * sg + bb.x, 0.f);
    o.y = fmaxf(ga.y + gb.y + (c0.y + c1.y + c2.y + c3.y) * sg + bb.y, 0.f);
    o.z = fmaxf(ga.z + gb.z + (c0.z + c1.z + c2.z + c3.z) * sg + bb.z, 0.f);
    o.w = fmaxf(ga.w + gb.w + (c0.w + c1.w + c2.w + c3.w) * sg + bb.w, 0.f);
    __stcs((float4*)&g_h[(size_t)e * Dd + d0], o);
}

// ---------------- merged precompute: permuted weights + bcat + bb ---------------
__device__ __forceinline__ int perm32(int p) {
    int j = p & 31;
    int f = ((j >> 1) & 3) * 8 + ((j >> 3) & 3) * 2 + (j & 1);
    return (p & ~31) | f;
}
__global__ void k_prep(const float* __restrict__ ew2, const float* __restrict__ eb2,
                       const float* __restrict__ n1w1, const float* __restrict__ n1b1,
                       const float* __restrict__ n1b2, const float* __restrict__ n2w1,
                       const float* __restrict__ n2w2) {
    int i = blockIdx.x * blockDim.x + threadIdx.x;
    const int base1 = Dd * WCAT_LD;
    const int base2 = base1 + 2 * Dd;
    const int base3 = base2 + Dd;
    const int base4 = base3 + Dd * WP_LD;
    if (i < base1) {
        int k = i / WCAT_LD, p = i - k * WCAT_LD;
        int lp = perm32(p);
        float v = 0.f;
        if (lp < Dd)            v = ew2[(size_t)k * Dd + lp];
        else if (lp < 2 * Dd)   v = g_w2p[(size_t)k * Dd + (lp - Dd)];
        g_wcat[i] = v;
    } else if (i < base2) {
        int j = i - base1;
        if (j < Dd) {
            g_bcat[j] = eb2[j];
        } else {
            int n = j - Dd;
            float s = n1b1[n];
            for (int k = 0; k < Dd; k++) s += eb2[k] * n1w1[(size_t)(Dd + k) * Dd + n];
            g_bcat[j] = s;
        }
    } else if (i < base3) {
        int m = i - base2;
        float s = 0.f;
        for (int k = 0; k < Dd; k++) s += n1b2[k] * n2w1[(size_t)(Dd + k) * Dd + m];
        g_bb[m] = s;
    } else if (i < base4) {
        int j = i - base3;
        int k = j / WP_LD, p = j - k * WP_LD;
        int lp = perm32(p);
        g_w12p[j] = (lp < Dd) ? g_w12[(size_t)k * Dd + lp] : 0.f;
    } else if (i < base4 + Dd * WP_LD) {
        int j = i - base4;
        int k = j / WP_LD, p = j - k * WP_LD;
        int lp = perm32(p);
        g_wn2p[j] = (lp < Dd) ? n2w2[(size_t)k * Dd + lp] : 0.f;
    }
}

// ---------------- graph layer norm: warp-per-row stats ---------------------------
__global__ void k_stats(const int* __restrict__ batch) {
    int n = blockIdx.x * 8 + (threadIdx.x >> 5);   // 8 warps/block, row per warp
    if (n >= Nn) return;
    int l = threadIdx.x & 31;
    float s = 0.f, q = 0.f;
    const float* xr = &g_xenc[(size_t)n * Dd];
    for (int d = l * 4; d < Dd; d += 128) {        // 32 lanes x float4, 3 iters (75 float4s)
        if (d + 4 <= Dd) {
            float4 v = *(const float4*)&xr[d];
            s += v.x + v.y + v.z + v.w;
            q += v.x * v.x + v.y * v.y + v.z * v.z + v.w * v.w;
        }
    }
    // Dd=300: 75 float4 groups; lanes 0..74 over 3 strides of 32 -> handled above
    // (d runs l*4, l*4+128, l*4+256; group index l, l+32, l+64 < 75 checked by d+4<=Dd)
#pragma unroll
    for (int o = 16; o; o >>= 1) {
        s += __shfl_down_sync(0xFFFFFFFFu, s, o);
        q += __shfl_down_sync(0xFFFFFFFFu, q, o);
    }
    if (l == 0) {
        int g = __ldg(&batch[n]);
        atomicAdd(&g_gsum[g], s);
        atomicAdd(&g_gsq[g], q);
        atomicAdd(&g_gcnt[g], 1.f);
    }
}
__global__ void k_finalize() {
    int g = threadIdx.x;
    if (g < Gg) {
        float denom = fmaxf(g_gcnt[g] * (float)Dd, 1.f);
        float mean = g_gsum[g] / denom;
        float var = g_gsq[g] / denom - mean * mean;
        g_gmean[g] = mean;
        g_grstd[g] = rsqrtf(var + EPSv);
    }
}
__global__ void k_apply(const int* __restrict__ batch,
                        const float* __restrict__ lnw, const float* __restrict__ lnb,
                        float* __restrict__ out) {
    int i = blockIdx.x * blockDim.x + threadIdx.x;
    if (i >= Nn * 75) return;
    int n = i / 75, d0 = (i - n * 75) * 4;
    int g = __ldg(&batch[n]);
    float mean = g_gmean[g], rstd = g_grstd[g];
    float4 x = *(const float4*)&g_xenc[(size_t)n * Dd + d0];
    float4 wv = __ldg((const float4*)&lnw[d0]);
    float4 bv = __ldg((const float4*)&lnb[d0]);
    float4 o;
    o.x = (x.x - mean) * rstd * wv.x + bv.x;
    o.y = (x.y - mean) * rstd * wv.y + bv.y;
    o.z = (x.z - mean) * rstd * wv.z + bv.z;
    o.w = (x.w - mean) * rstd * wv.w + bv.w;
    __stcs((float4*)&out[(size_t)n * Dd + d0], o);
}

// ---------------- launch ---------------------------------------------------------
static float* symf(const void* s) {
    void* p = nullptr;
    cudaGetSymbolAddress(&p, s);
    return (float*)p;
}

extern "C" void kernel_launch(void* const* d_in, const int* in_sizes, int n_in,
                              void* d_out, int out_size) {
    const int*   x_tok  = (const int*)d_in[0];
    const int*   ea_tok = (const int*)d_in[1];
    const int*   eidx   = (const int*)d_in[2];
    const int*   ase    = (const int*)d_in[3];
    const int*   batch  = (const int*)d_in[4];
    const float* emb    = (const float*)d_in[5];
    const float* ew1  = (const float*)d_in[6];
    const float* eb1  = (const float*)d_in[7];
    const float* ew2  = (const float*)d_in[8];
    const float* eb2  = (const float*)d_in[9];
    const float* n1w1 = (const float*)d_in[10];
    const float* n1b1 = (const float*)d_in[11];
    const float* n1w2 = (const float*)d_in[12];
    const float* n1b2 = (const float*)d_in[13];
    const float* n2w1 = (const float*)d_in[14];
    const float* n2b1 = (const float*)d_in[15];
    const float* n2w2 = (const float*)d_in[16];
    const float* n2b2 = (const float*)d_in[17];
    const float* lnw  = (const float*)d_in[18];
    const float* lnb  = (const float*)d_in[19];

    const int* row = eidx;
    const int* col = eidx + Ee;

    float* out = (float*)d_out;
    float* edge_out = out + (size_t)Nn * Dd;

    float* pembA = symf(g_embA); float* pembB = symf(g_embB);
    float* pembC = symf(g_embC); float* pembD = symf(g_embD);
    float* pembF = symf(g_embF);
    float* pgsD  = symf(g_gsD);  float* pgsF  = symf(g_gsF);
    float* ph    = symf(g_h);
    float* pagg  = symf(g_agg);  float* pxenc = symf(g_xenc);
    float* pw2p  = symf(g_w2p);  float* pw12  = symf(g_w12);
    float* pwcat = symf(g_wcat); float* pbcat = symf(g_bcat);
    float* pw12p = symf(g_w12p); float* pwn2p = symf(g_wn2p);
    float* pbb   = symf(g_bb);   float* pcnt  = symf(g_cnt);

    const int T256 = 256;

    k_init<<<2048, T256>>>();

    {
        Bat5 b;
        b.A[0] = emb; b.A[1] = emb; b.A[2] = emb; b.A[3] = emb; b.A[4] = emb;
        b.W[0] = ew1; b.W[1] = ew1 + 300*300; b.W[2] = ew1 + 600*300;
        b.W[3] = n1w1; b.W[4] = n2w1;
        b.O[0] = pembA; b.O[1] = pembB; b.O[2] = pembC; b.O[3] = pembD; b.O[4] = pembF;
        k_gemm_bat<<<dim3(5, (Vv + BMt - 1) / BMt, 5), T256>>>(Vv, Dd, b, Dd);
    }
    {
        Bat5 b;
        b.A[0] = ew2;  b.A[1] = n1w2; b.A[2] = ew2; b.A[3] = ew2; b.A[4] = ew2;
        b.W[0] = n1w1 + 300*300; b.W[1] = n2w1 + 300*300;
        b.W[2] = b.W[0]; b.W[3] = b.W[0]; b.W[4] = b.W[0];
        b.O[0] = pw2p; b.O[1] = pw12; b.O[2] = pw2p; b.O[3] = pw2p; b.O[4] = pw2p;
        k_gemm_bat<<<dim3(5, (Dd + BMt - 1) / BMt, 2), T256>>>(Dd, Dd, b, Dd);
    }
    int prepN = Dd * WCAT_LD + 3 * Dd + 2 * Dd * WP_LD;
    k_prep<<<(prepN + T256 - 1) / T256, T256>>>(ew2, eb2, n1w1, n1b1, n1b2, n2w1, n2w2);

    // gather-sums (+ folded sign set & degree histogram) + edge layer-1
    k_gsum4<<<(Nn * 75 + T256 - 1) / T256, T256>>>(x_tok, ase, col);
    k_edge_l1<<<(Ee * 75 + T256 - 1) / T256, T256>>>(ea_tok, row, col, eb1);

    // dual GEMM (permuted, ldw=640)
    k_gemm_tc<3><<<dim3(10, Ee / BMt), T256>>>(Ee, WCAT_LD, ph, nullptr, pwcat, WCAT_LD,
                                               pbcat, nullptr, edge_out, pagg,
                                               pgsD, row, col, nullptr);
    // node2 layer-1 (permuted): relu(agg@w12/cnt + n2b1 + gsF + (cnt>0)bb)
    dim3 gN(5, (Nn + BMt - 1) / BMt);
    k_gemm_tc<6><<<gN, T256>>>(Nn, WP_LD, pagg, nullptr, pw12p, WP_LD, n2b1, pbb,
                               ph, nullptr, pgsF, nullptr, nullptr, pcnt);
    // node2 layer-2 (permuted)
    k_gemm_tc<1><<<gN, T256>>>(Nn, WP_LD, ph, nullptr, pwn2p, WP_LD, n2b2, nullptr,
                               pxenc, nullptr, nullptr, nullptr, nullptr, nullptr);

    k_stats<<<(Nn + 7) / 8, T256>>>(batch);
    k_finalize<<<1, 128>>>();
    k_apply<<<(Nn * 75 + T256 - 1) / T256, T256>>>(batch, lnw, lnb, out);
}